// round 6
// baseline (speedup 1.0000x reference)
#include <cuda_runtime.h>
#include <cuda_bf16.h>
#include <cstdint>

#define Bb 8
#define Nn 2048
#define Mm 2048
#define DIN 512
#define Hh 256

// ---------------- scratch (device globals; no allocs allowed) ----------------
__device__ uint32_t g_qfH[(size_t)Bb*Nn*DIN/2], g_qfL[(size_t)Bb*Nn*DIN/2];
__device__ uint32_t g_vrH[(size_t)Bb*Mm*DIN/2], g_vrL[(size_t)Bb*Mm*DIN/2];
// weights packed n-major: [n][kp]. Wqs..Wve (6 x 256x256), W1 (256x512), W2 (256x128)
__device__ uint32_t g_wH[6*65536 + 131072 + 32768], g_wL[6*65536 + 131072 + 32768];
__device__ uint32_t g_qsH[(size_t)Bb*Nn*128], g_qsL[(size_t)Bb*Nn*128];
__device__ uint32_t g_qeH[(size_t)Bb*Nn*128], g_qeL[(size_t)Bb*Nn*128];
__device__ uint32_t g_ksH[(size_t)Bb*Mm*128], g_ksL[(size_t)Bb*Mm*128];
__device__ uint32_t g_keH[(size_t)Bb*Mm*128], g_keL[(size_t)Bb*Mm*128];
__device__ float    g_vs[(size_t)Bb*Mm*Hh], g_ve[(size_t)Bb*Mm*Hh];
__device__ uint32_t g_vsTH[(size_t)Bb*Hh*1024], g_vsTL[(size_t)Bb*Hh*1024];
__device__ uint32_t g_veTH[(size_t)Bb*Hh*1024], g_veTL[(size_t)Bb*Hh*1024];
__device__ float    g_L[(size_t)Bb*Nn*Mm];
__device__ float    g_D[(size_t)Bb*Nn*Mm];
__device__ uint32_t g_pH[(size_t)Bb*Nn*1024], g_pL[(size_t)Bb*Nn*1024];
__device__ uint32_t g_fH[(size_t)Bb*Nn*512], g_fL[(size_t)Bb*Nn*512];
__device__ uint32_t g_hH[(size_t)Bb*Nn*128], g_hL[(size_t)Bb*Nn*128];
__device__ float g_q2[Bb*Nn], g_k2[Bb*Mm], g_dsum[Bb], g_scale[Bb];

// ---------------- helpers ----------------
__device__ __forceinline__ void split2(float f0, float f1, uint32_t& H, uint32_t& L) {
    __nv_bfloat16 h0 = __float2bfloat16(f0);
    __nv_bfloat16 h1 = __float2bfloat16(f1);
    __nv_bfloat16 l0 = __float2bfloat16(f0 - __bfloat162float(h0));
    __nv_bfloat16 l1 = __float2bfloat16(f1 - __bfloat162float(h1));
    H = (uint32_t)__bfloat16_as_ushort(h0) | ((uint32_t)__bfloat16_as_ushort(h1) << 16);
    L = (uint32_t)__bfloat16_as_ushort(l0) | ((uint32_t)__bfloat16_as_ushort(l1) << 16);
}
__device__ __forceinline__ float bflo(uint32_t u) {
    return __bfloat162float(__ushort_as_bfloat16((unsigned short)(u & 0xffff)));
}
__device__ __forceinline__ float bfhi(uint32_t u) {
    return __bfloat162float(__ushort_as_bfloat16((unsigned short)(u >> 16)));
}
__device__ __forceinline__ void mmabf(float* d, const uint32_t* a, uint32_t b0, uint32_t b1) {
    asm volatile(
        "mma.sync.aligned.m16n8k16.row.col.f32.bf16.bf16.f32 "
        "{%0,%1,%2,%3}, {%4,%5,%6,%7}, {%8,%9}, {%0,%1,%2,%3};\n"
        : "+f"(d[0]), "+f"(d[1]), "+f"(d[2]), "+f"(d[3])
        : "r"(a[0]), "r"(a[1]), "r"(a[2]), "r"(a[3]), "r"(b0), "r"(b1));
}
__device__ __forceinline__ void ldsm4(uint32_t* r, uint32_t a) {
    asm volatile("ldmatrix.sync.aligned.m8n8.x4.shared.b16 {%0,%1,%2,%3}, [%4];"
        : "=r"(r[0]), "=r"(r[1]), "=r"(r[2]), "=r"(r[3]) : "r"(a));
}
__device__ __forceinline__ uint32_t smem_u32(const void* p) {
    return (uint32_t)__cvta_generic_to_shared(p);
}
__device__ __forceinline__ void cpa16(void* smem, const void* gmem) {
    uint32_t s = (uint32_t)__cvta_generic_to_shared(smem);
    asm volatile("cp.async.cg.shared.global [%0], [%1], 16;\n" :: "r"(s), "l"(gmem));
}
#define CP_COMMIT() asm volatile("cp.async.commit_group;\n")
#define CP_WAIT1()  asm volatile("cp.async.wait_group 1;\n")
#define CP_WAIT0()  asm volatile("cp.async.wait_group 0;\n")

__device__ __forceinline__ float warpRedSum(float v) {
#pragma unroll
    for (int o = 16; o > 0; o >>= 1) v += __shfl_xor_sync(0xffffffffu, v, o);
    return v;
}
__device__ __forceinline__ float warpRedMax(float v) {
#pragma unroll
    for (int o = 16; o > 0; o >>= 1) v = fmaxf(v, __shfl_xor_sync(0xffffffffu, v, o));
    return v;
}

// ---------------- prep kernels ----------------
__global__ void pack_rows_kernel(const float* __restrict__ src,
                                 uint32_t* __restrict__ H, uint32_t* __restrict__ L,
                                 int npairs) {
    int i = blockIdx.x * 256 + threadIdx.x;
    if (i >= npairs) return;
    float2 f = ((const float2*)src)[i];
    uint32_t h, l; split2(f.x, f.y, h, l);
    H[i] = h; L[i] = l;
}
// weights -> [n][kp] (n-major, ldmatrix-friendly)
__global__ void pack_weight_kernel(const float* __restrict__ W,
                                   uint32_t* __restrict__ H, uint32_t* __restrict__ L,
                                   int Kp, int Nc) {
    int i = blockIdx.x * 256 + threadIdx.x;
    if (i >= Kp * Nc) return;
    int n = i / Kp, kp = i - n * Kp;
    float f0 = W[(size_t)(2 * kp) * Nc + n];
    float f1 = W[(size_t)(2 * kp + 1) * Nc + n];
    uint32_t h, l; split2(f0, f1, h, l);
    H[i] = h; L[i] = l;
}
__global__ void transpose_pack_kernel(const float* __restrict__ V,
                                      uint32_t* __restrict__ H, uint32_t* __restrict__ L) {
    __shared__ float t[64][33];
    const int b = blockIdx.z, m0 = blockIdx.x * 64, h0 = blockIdx.y * 32;
    const int tid = threadIdx.x;
#pragma unroll
    for (int it = 0; it < 2; it++) {
        int i = tid + it * 256;
        int m = i >> 3, h4 = (i & 7) * 4;
        float4 v = *(const float4*)&V[((size_t)b * Mm + m0 + m) * Hh + h0 + h4];
        t[m][h4 + 0] = v.x; t[m][h4 + 1] = v.y; t[m][h4 + 2] = v.z; t[m][h4 + 3] = v.w;
    }
    __syncthreads();
#pragma unroll
    for (int u = 0; u < 4; u++) {
        int i = tid + u * 256;
        int h = i >> 5, mp = i & 31;
        float f0 = t[2 * mp][h], f1 = t[2 * mp + 1][h];
        uint32_t hh, ll; split2(f0, f1, hh, ll);
        size_t o = ((size_t)b * Hh + h0 + h) * 1024 + (m0 >> 1) + mp;
        H[o] = hh; L[o] = ll;
    }
}
__global__ void rowsumsq_kernel(const uint32_t* __restrict__ H, const uint32_t* __restrict__ L,
                                float* __restrict__ dst) {
    const int row = blockIdx.x, tid = threadIdx.x;
    uint32_t h = H[(size_t)row * 128 + tid], l = L[(size_t)row * 128 + tid];
    float v0 = bflo(h) + bflo(l), v1 = bfhi(h) + bfhi(l);
    float s = v0 * v0 + v1 * v1;
    __shared__ float sh[4];
    int lane = tid & 31, wid = tid >> 5;
    float w = warpRedSum(s);
    if (lane == 0) sh[wid] = w;
    __syncthreads();
    if (wid == 0) {
        float t = (lane < 4) ? sh[lane] : 0.0f;
        t = warpRedSum(t);
        if (lane == 0) dst[row] = t;
    }
}
__global__ void zero_dsum_kernel() { if (threadIdx.x < Bb) g_dsum[threadIdx.x] = 0.0f; }
__global__ void finalize_scale_kernel() {
    if (threadIdx.x < Bb)
        g_scale[threadIdx.x] = fmaxf(g_dsum[threadIdx.x] * (1.0f / ((float)Nn * (float)Mm)), 1e-4f);
}

// =============================================================================
// Packed bf16x3 GEMM with ldmatrix. C[R,Nc] = A[R,K] @ W + bias (+SiLU/pack).
// Tile 128x128, BK=32 (16 kp), 2-stage cp.async, 8 warps (4x2), warp 32x64.
// smem u32 layout: AH[2][128][20] AL BH[2][128][20] BL  (n-major B).
// =============================================================================
__global__ __launch_bounds__(256, 2) void gemmP_kernel(
    const uint32_t* __restrict__ aH, const uint32_t* __restrict__ aL,
    const uint32_t* __restrict__ wH, const uint32_t* __restrict__ wL,
    const float* __restrict__ bias,
    float* __restrict__ outF, uint32_t* __restrict__ outH, uint32_t* __restrict__ outL,
    int Kp, int Nc, int act, int packedOut)
{
    extern __shared__ uint32_t smu[];
    uint32_t* smA_H = smu;                 // 2*128*20 = 5120 u32 each
    uint32_t* smA_L = smA_H + 5120;
    uint32_t* smB_H = smA_L + 5120;
    uint32_t* smB_L = smB_H + 5120;
    const uint32_t SB = smem_u32(smu);
    const uint32_t bAH = SB, bAL = SB + 5120 * 4, bBH = SB + 10240 * 4, bBL = SB + 15360 * 4;

    const int row0 = blockIdx.y * 128;
    const int col0 = blockIdx.x * 128;
    const int tid  = threadIdx.x;
    const int lane = tid & 31, warp = tid >> 5;
    const int wR = warp >> 1, wC = warp & 1;

    float acc[2][8][4] = {};
    const int nk = Kp / 16;

    const int rA = wR * 32 + (lane & 7) + ((lane >> 3) & 1) * 8;  // + i*16
    const int rB = wC * 64 + (lane & 7) + ((lane >> 3) & 1) * 8;  // + jj*16
    const uint32_t co = ((lane >> 4) & 1) * 4;

    {   // prologue stage 0
#pragma unroll
        for (int it = 0; it < 2; it++) {
            int i = tid + it * 256;
            int r = i >> 2, c4 = (i & 3) * 4;
            size_t ga = (size_t)(row0 + r) * Kp + c4;
            cpa16(&smA_H[(size_t)r * 20 + c4], aH + ga);
            cpa16(&smA_L[(size_t)r * 20 + c4], aL + ga);
            size_t gb = (size_t)(col0 + r) * Kp + c4;
            cpa16(&smB_H[(size_t)r * 20 + c4], wH + gb);
            cpa16(&smB_L[(size_t)r * 20 + c4], wL + gb);
        }
        CP_COMMIT();
    }

    for (int kt = 0; kt < nk; kt++) {
        const int s = kt & 1;
        if (kt + 1 < nk) {
            const int sn = s ^ 1;
            const int k0 = (kt + 1) * 16;
#pragma unroll
            for (int it = 0; it < 2; it++) {
                int i = tid + it * 256;
                int r = i >> 2, c4 = (i & 3) * 4;
                size_t ga = (size_t)(row0 + r) * Kp + k0 + c4;
                cpa16(&smA_H[(size_t)(sn * 128 + r) * 20 + c4], aH + ga);
                cpa16(&smA_L[(size_t)(sn * 128 + r) * 20 + c4], aL + ga);
                size_t gb = (size_t)(col0 + r) * Kp + k0 + c4;
                cpa16(&smB_H[(size_t)(sn * 128 + r) * 20 + c4], wH + gb);
                cpa16(&smB_L[(size_t)(sn * 128 + r) * 20 + c4], wL + gb);
            }
            CP_COMMIT();
            CP_WAIT1();
        } else {
            CP_WAIT0();
        }
        __syncthreads();
#pragma unroll
        for (int ks = 0; ks < 2; ks++) {
            uint32_t ah[2][4], al[2][4];
#pragma unroll
            for (int i = 0; i < 2; i++) {
                uint32_t off = ((uint32_t)(s * 128 + rA + i * 16) * 20 + ks * 8 + co) * 4;
                ldsm4(ah[i], bAH + off);
                ldsm4(al[i], bAL + off);
            }
#pragma unroll
            for (int jj = 0; jj < 4; jj++) {
                uint32_t offb = ((uint32_t)(s * 128 + rB + jj * 16) * 20 + ks * 8 + co) * 4;
                uint32_t bh[4], bl[4];
                ldsm4(bh, bBH + offb);
                ldsm4(bl, bBL + offb);
#pragma unroll
                for (int s0 = 0; s0 < 2; s0++) {
                    int j = jj * 2 + s0;
#pragma unroll
                    for (int i = 0; i < 2; i++) {
                        mmabf(acc[i][j], ah[i], bh[s0], bh[2 + s0]);
                        mmabf(acc[i][j], ah[i], bl[s0], bl[2 + s0]);
                        mmabf(acc[i][j], al[i], bh[s0], bh[2 + s0]);
                    }
                }
            }
        }
        __syncthreads();
    }
#pragma unroll
    for (int i = 0; i < 2; i++) {
        int r = row0 + wR * 32 + i * 16 + (lane >> 2);
#pragma unroll
        for (int j = 0; j < 8; j++) {
            int c = col0 + wC * 64 + j * 8 + 2 * (lane & 3);
            float b0 = bias[c], b1 = bias[c + 1];
            float v0 = acc[i][j][0] + b0, v1 = acc[i][j][1] + b1;
            float v2 = acc[i][j][2] + b0, v3 = acc[i][j][3] + b1;
            if (act) {
                v0 = v0 / (1.0f + __expf(-v0));
                v1 = v1 / (1.0f + __expf(-v1));
                v2 = v2 / (1.0f + __expf(-v2));
                v3 = v3 / (1.0f + __expf(-v3));
            }
            if (packedOut) {
                uint32_t hh, ll;
                size_t o0 = (size_t)r * (Nc >> 1) + (c >> 1);
                split2(v0, v1, hh, ll); outH[o0] = hh; outL[o0] = ll;
                size_t o1 = (size_t)(r + 8) * (Nc >> 1) + (c >> 1);
                split2(v2, v3, hh, ll); outH[o1] = hh; outL[o1] = ll;
            } else {
                *(float2*)&outF[(size_t)r * Nc + c]       = make_float2(v0, v1);
                *(float2*)&outF[(size_t)(r + 8) * Nc + c] = make_float2(v2, v3);
            }
        }
    }
}

// =============================================================================
// Logits: dual packed-bf16x3 NT GEMM + dist/pi epilogue + dist-sum. ldmatrix.
// Block 128(n) x 64(m), BK=16 (8 kp/stage), 2-stage cp.async, 72KB dyn smem.
// =============================================================================
__global__ __launch_bounds__(256) void logitsP_kernel(
    const float* __restrict__ pi_star, const float* __restrict__ gamma_p)
{
    extern __shared__ uint32_t smu[];
    uint32_t* smQsH = smu;                  // 2*128*12 = 3072 each
    uint32_t* smQsL = smQsH + 3072;
    uint32_t* smQeH = smQsL + 3072;
    uint32_t* smQeL = smQeH + 3072;
    uint32_t* smKsH = smQeL + 3072;         // 2*64*12 = 1536 each
    uint32_t* smKsL = smKsH + 1536;
    uint32_t* smKeH = smKsL + 1536;
    uint32_t* smKeL = smKeH + 1536;
    const uint32_t SB = smem_u32(smu);
    const uint32_t bQsH = SB,              bQsL = SB + 3072 * 4;
    const uint32_t bQeH = SB + 6144 * 4,   bQeL = SB + 9216 * 4;
    const uint32_t bKsH = SB + 12288 * 4,  bKsL = SB + 13824 * 4;
    const uint32_t bKeH = SB + 15360 * 4,  bKeL = SB + 16896 * 4;

    const int b  = blockIdx.z;
    const int n0 = blockIdx.y * 128;
    const int m0 = blockIdx.x * 64;
    const int tid = threadIdx.x;
    const int lane = tid & 31, warp = tid >> 5;
    const int wR = warp >> 1, wC = warp & 1;

    const uint32_t* qsH = g_qsH + (size_t)(b * Nn + n0) * 128;
    const uint32_t* qsL = g_qsL + (size_t)(b * Nn + n0) * 128;
    const uint32_t* qeH = g_qeH + (size_t)(b * Nn + n0) * 128;
    const uint32_t* qeL = g_qeL + (size_t)(b * Nn + n0) * 128;
    const uint32_t* kH  = (tid < 128) ? g_ksH + (size_t)(b * Mm + m0) * 128
                                      : g_keH + (size_t)(b * Mm + m0) * 128;
    const uint32_t* kL  = (tid < 128) ? g_ksL + (size_t)(b * Mm + m0) * 128
                                      : g_keL + (size_t)(b * Mm + m0) * 128;

    float accS[2][4][4] = {}, accE[2][4][4] = {};
    const int nk = 16;   // 128 kpairs / 8

    const int qr = tid >> 1, qc4 = (tid & 1) * 4;
    const int kt_ = tid & 127;
    const int kr = kt_ >> 1, kc4 = (kt_ & 1) * 4;
    uint32_t* dstKH = (tid < 128) ? smKsH : smKeH;
    uint32_t* dstKL = (tid < 128) ? smKsL : smKeL;

    const int rA = wR * 32 + (lane & 7) + ((lane >> 3) & 1) * 8;
    const int rB = wC * 32 + (lane & 7) + ((lane >> 3) & 1) * 8;
    const uint32_t co = ((lane >> 4) & 1) * 4;

    {   // prologue
        size_t gq = (size_t)qr * 128 + qc4;
        cpa16(&smQsH[(size_t)qr * 12 + qc4], qsH + gq);
        cpa16(&smQsL[(size_t)qr * 12 + qc4], qsL + gq);
        cpa16(&smQeH[(size_t)qr * 12 + qc4], qeH + gq);
        cpa16(&smQeL[(size_t)qr * 12 + qc4], qeL + gq);
        size_t gk = (size_t)kr * 128 + kc4;
        cpa16(&dstKH[(size_t)kr * 12 + kc4], kH + gk);
        cpa16(&dstKL[(size_t)kr * 12 + kc4], kL + gk);
        CP_COMMIT();
    }

    for (int kt = 0; kt < nk; kt++) {
        const int s = kt & 1;
        if (kt + 1 < nk) {
            const int sn = s ^ 1;
            const int k0 = (kt + 1) * 8;
            size_t gq = (size_t)qr * 128 + k0 + qc4;
            cpa16(&smQsH[(size_t)(sn * 128 + qr) * 12 + qc4], qsH + gq);
            cpa16(&smQsL[(size_t)(sn * 128 + qr) * 12 + qc4], qsL + gq);
            cpa16(&smQeH[(size_t)(sn * 128 + qr) * 12 + qc4], qeH + gq);
            cpa16(&smQeL[(size_t)(sn * 128 + qr) * 12 + qc4], qeL + gq);
            size_t gk = (size_t)kr * 128 + k0 + kc4;
            cpa16(&dstKH[(size_t)(sn * 64 + kr) * 12 + kc4], kH + gk);
            cpa16(&dstKL[(size_t)(sn * 64 + kr) * 12 + kc4], kL + gk);
            CP_COMMIT();
            CP_WAIT1();
        } else {
            CP_WAIT0();
        }
        __syncthreads();

        uint32_t qsh[2][4], qsl[2][4], qeh[2][4], qel[2][4];
#pragma unroll
        for (int i = 0; i < 2; i++) {
            uint32_t off = ((uint32_t)(s * 128 + rA + i * 16) * 12 + co) * 4;
            ldsm4(qsh[i], bQsH + off);
            ldsm4(qsl[i], bQsL + off);
            ldsm4(qeh[i], bQeH + off);
            ldsm4(qel[i], bQeL + off);
        }
#pragma unroll
        for (int jj = 0; jj < 2; jj++) {
            uint32_t offb = ((uint32_t)(s * 64 + rB + jj * 16) * 12 + co) * 4;
            uint32_t ksh[4], ksl[4], keh[4], kel[4];
            ldsm4(ksh, bKsH + offb);
            ldsm4(ksl, bKsL + offb);
            ldsm4(keh, bKeH + offb);
            ldsm4(kel, bKeL + offb);
#pragma unroll
            for (int s0 = 0; s0 < 2; s0++) {
                int j = jj * 2 + s0;
#pragma unroll
                for (int i = 0; i < 2; i++) {
                    mmabf(accS[i][j], qsh[i], ksh[s0], ksh[2 + s0]);
                    mmabf(accS[i][j], qsh[i], ksl[s0], ksl[2 + s0]);
                    mmabf(accS[i][j], qsl[i], ksh[s0], ksh[2 + s0]);
                    mmabf(accE[i][j], qeh[i], keh[s0], keh[2 + s0]);
                    mmabf(accE[i][j], qeh[i], kel[s0], kel[2 + s0]);
                    mmabf(accE[i][j], qel[i], keh[s0], keh[2 + s0]);
                }
            }
        }
        __syncthreads();
    }

    const float g = gamma_p[0];
    float sumd = 0.0f;
#pragma unroll
    for (int i = 0; i < 2; i++) {
        int n_lo = n0 + wR * 32 + i * 16 + (lane >> 2);
        float q2a = g_q2[b * Nn + n_lo];
        float q2b = g_q2[b * Nn + n_lo + 8];
#pragma unroll
        for (int j = 0; j < 4; j++) {
            int m = m0 + wC * 32 + j * 8 + 2 * (lane & 3);
            float k2a = g_k2[b * Mm + m], k2b = g_k2[b * Mm + m + 1];
            size_t base0 = ((size_t)b * Nn + n_lo) * Mm + m;
            float2 piv = *(const float2*)&pi_star[base0];
            float d0 = sqrtf(fmaxf(q2a + k2a - 2.0f * accE[i][j][0], 1e-12f));
            float d1 = sqrtf(fmaxf(q2a + k2b - 2.0f * accE[i][j][1], 1e-12f));
            sumd += d0 + d1;
            *(float2*)&g_D[base0] = make_float2(d0, d1);
            float L0 = accS[i][j][0] * 0.0625f + g * __logf(fmaxf(piv.x, 1e-9f));
            float L1 = accS[i][j][1] * 0.0625f + g * __logf(fmaxf(piv.y, 1e-9f));
            *(float2*)&g_L[base0] = make_float2(L0, L1);
            size_t base1 = ((size_t)b * Nn + n_lo + 8) * Mm + m;
            piv = *(const float2*)&pi_star[base1];
            float d2v = sqrtf(fmaxf(q2b + k2a - 2.0f * accE[i][j][2], 1e-12f));
            float d3v = sqrtf(fmaxf(q2b + k2b - 2.0f * accE[i][j][3], 1e-12f));
            sumd += d2v + d3v;
            *(float2*)&g_D[base1] = make_float2(d2v, d3v);
            float L2 = accS[i][j][2] * 0.0625f + g * __logf(fmaxf(piv.x, 1e-9f));
            float L3 = accS[i][j][3] * 0.0625f + g * __logf(fmaxf(piv.y, 1e-9f));
            *(float2*)&g_L[base1] = make_float2(L2, L3);
        }
    }
    float* red = (float*)smu;
    red[tid] = sumd;
    __syncthreads();
    for (int sred = 128; sred > 0; sred >>= 1) {
        if (tid < sred) red[tid] += red[tid + sred];
        __syncthreads();
    }
    if (tid == 0) atomicAdd(&g_dsum[b], red[0]);
}

// =============================================================================
// Ctx: dual packed-bf16x3 NN GEMM attn@Vs/attn@Ve -> fused packed. ldmatrix.
// Block 128(n) x 64(h), BK=32 (16 kp/stage), 2-stage cp.async, 80KB dyn smem.
// =============================================================================
__global__ __launch_bounds__(256, 2) void ctxP_kernel()
{
    extern __shared__ uint32_t smu[];
    uint32_t* smPH  = smu;                  // 2*128*20 = 5120 each
    uint32_t* smPL  = smPH + 5120;
    uint32_t* smVsH = smPL + 5120;          // 2*64*20 = 2560 each
    uint32_t* smVsL = smVsH + 2560;
    uint32_t* smVeH = smVsL + 2560;
    uint32_t* smVeL = smVeH + 2560;
    const uint32_t SB = smem_u32(smu);
    const uint32_t bPH  = SB,               bPL  = SB + 5120 * 4;
    const uint32_t bVsH = SB + 10240 * 4,   bVsL = SB + 12800 * 4;
    const uint32_t bVeH = SB + 15360 * 4,   bVeL = SB + 17920 * 4;

    const int b  = blockIdx.z;
    const int n0 = blockIdx.y * 128;
    const int h0 = blockIdx.x * 64;
    const int tid = threadIdx.x;
    const int lane = tid & 31, warp = tid >> 5;
    const int wR = warp >> 1, wC = warp & 1;

    const uint32_t* pH = g_pH + (size_t)(b * Nn + n0) * 1024;
    const uint32_t* pL = g_pL + (size_t)(b * Nn + n0) * 1024;
    const uint32_t* vsH = g_vsTH + ((size_t)b * Hh + h0) * 1024;
    const uint32_t* vsL = g_vsTL + ((size_t)b * Hh + h0) * 1024;
    const uint32_t* veH = g_veTH + ((size_t)b * Hh + h0) * 1024;
    const uint32_t* veL = g_veTL + ((size_t)b * Hh + h0) * 1024;

    float accS[2][4][4] = {}, accE[2][4][4] = {};
    const int nk = 64;   // 1024 mpairs / 16

    const int rA = wR * 32 + (lane & 7) + ((lane >> 3) & 1) * 8;
    const int rB = wC * 32 + (lane & 7) + ((lane >> 3) & 1) * 8;
    const uint32_t co = ((lane >> 4) & 1) * 4;

    // V rows: 64 rows x 16 u32 per plane -> 256 cpa16 per plane; 1/thread
    const int vr = tid >> 2, vc4 = (tid & 3) * 4;

    {   // prologue
#pragma unroll
        for (int it = 0; it < 2; it++) {
            int i = tid + it * 256;
            int r = i >> 2, c4 = (i & 3) * 4;
            size_t gp = (size_t)r * 1024 + c4;
            cpa16(&smPH[(size_t)r * 20 + c4], pH + gp);
            cpa16(&smPL[(size_t)r * 20 + c4], pL + gp);
        }
        {
            size_t gv = (size_t)vr * 1024 + vc4;
            cpa16(&smVsH[(size_t)vr * 20 + vc4], vsH + gv);
            cpa16(&smVsL[(size_t)vr * 20 + vc4], vsL + gv);
            cpa16(&smVeH[(size_t)vr * 20 + vc4], veH + gv);
            cpa16(&smVeL[(size_t)vr * 20 + vc4], veL + gv);
        }
        CP_COMMIT();
    }

    for (int kt = 0; kt < nk; kt++) {
        const int s = kt & 1;
        if (kt + 1 < nk) {
            const int sn = s ^ 1;
            const int mp0 = (kt + 1) * 16;
#pragma unroll
            for (int it = 0; it < 2; it++) {
                int i = tid + it * 256;
                int r = i >> 2, c4 = (i & 3) * 4;
                size_t gp = (size_t)r * 1024 + mp0 + c4;
                cpa16(&smPH[(size_t)(sn * 128 + r) * 20 + c4], pH + gp);
                cpa16(&smPL[(size_t)(sn * 128 + r) * 20 + c4], pL + gp);
            }
            {
                size_t gv = (size_t)vr * 1024 + mp0 + vc4;
                cpa16(&smVsH[(size_t)(sn * 64 + vr) * 20 + vc4], vsH + gv);
                cpa16(&smVsL[(size_t)(sn * 64 + vr) * 20 + vc4], vsL + gv);
                cpa16(&smVeH[(size_t)(sn * 64 + vr) * 20 + vc4], veH + gv);
                cpa16(&smVeL[(size_t)(sn * 64 + vr) * 20 + vc4], veL + gv);
            }
            CP_COMMIT();
            CP_WAIT1();
        } else {
            CP_WAIT0();
        }
        __syncthreads();
#pragma unroll
        for (int ks = 0; ks < 2; ks++) {
            uint32_t ph[2][4], pl[2][4];
#pragma unroll
            for (int i = 0; i < 2; i++) {
                uint32_t off = ((uint32_t)(s * 128 + rA + i * 16) * 20 + ks * 8 + co) * 4;
                ldsm4(ph[i], bPH + off);
                ldsm4(pl[i], bPL + off);
            }
#pragma unroll
            for (int jj = 0; jj < 2; jj++) {
                uint32_t offb = ((uint32_t)(s * 64 + rB + jj * 16) * 20 + ks * 8 + co) * 4;
                uint32_t vsh[4], vsl[4], veh[4], vel[4];
                ldsm4(vsh, bVsH + offb);
                ldsm4(vsl, bVsL + offb);
                ldsm4(veh, bVeH + offb);
                ldsm4(vel, bVeL + offb);
#pragma unroll
                for (int s0 = 0; s0 < 2; s0++) {
                    int j = jj * 2 + s0;
#pragma unroll
                    for (int i = 0; i < 2; i++) {
                        mmabf(accS[i][j], ph[i], vsh[s0], vsh[2 + s0]);
                        mmabf(accS[i][j], ph[i], vsl[s0], vsl[2 + s0]);
                        mmabf(accS[i][j], pl[i], vsh[s0], vsh[2 + s0]);
                        mmabf(accE[i][j], ph[i], veh[s0], veh[2 + s0]);
                        mmabf(accE[i][j], ph[i], vel[s0], vel[2 + s0]);
                        mmabf(accE[i][j], pl[i], veh[s0], veh[2 + s0]);
                    }
                }
            }
        }
        __syncthreads();
    }
#pragma unroll
    for (int i = 0; i < 2; i++) {
        int n_lo = n0 + wR * 32 + i * 16 + (lane >> 2);
#pragma unroll
        for (int j = 0; j < 4; j++) {
            int h = h0 + wC * 32 + j * 8 + 2 * (lane & 3);
#pragma unroll
            for (int half = 0; half < 2; half++) {
                int n = n_lo + half * 8;
                float cs0 = accS[i][j][half * 2 + 0], cs1 = accS[i][j][half * 2 + 1];
                float ce0 = accE[i][j][half * 2 + 0], ce1 = accE[i][j][half * 2 + 1];
                size_t fb = ((size_t)b * Nn + n) * 512;
                uint32_t hh, ll;
                split2(cs0, cs1, hh, ll);
                g_fH[fb + (h >> 1)] = hh;             g_fL[fb + (h >> 1)] = ll;
                split2(ce0, ce1, hh, ll);
                g_fH[fb + 128 + (h >> 1)] = hh;       g_fL[fb + 128 + (h >> 1)] = ll;
                split2(cs0 - ce0, cs1 - ce1, hh, ll);
                g_fH[fb + 256 + (h >> 1)] = hh;       g_fL[fb + 256 + (h >> 1)] = ll;
                split2(cs0 * ce0, cs1 * ce1, hh, ll);
                g_fH[fb + 384 + (h >> 1)] = hh;       g_fL[fb + 384 + (h >> 1)] = ll;
            }
        }
    }
}

// ---------------- softmax ----------------
__global__ void softmax_kernel(const float* __restrict__ ew_p) {
    const int row = blockIdx.x;
    const int b   = row / Nn;
    const float invsc = ew_p[0] / g_scale[b];
    const size_t base = (size_t)row * Mm;
    const int c0 = threadIdx.x * 8;
    float v[8];
    float mx = -1e30f;
#pragma unroll
    for (int q = 0; q < 2; q++) {
        float4 lv = *(const float4*)&g_L[base + c0 + q * 4];
        float4 dv = *(const float4*)&g_D[base + c0 + q * 4];
        v[q*4+0] = lv.x - dv.x * invsc; v[q*4+1] = lv.y - dv.y * invsc;
        v[q*4+2] = lv.z - dv.z * invsc; v[q*4+3] = lv.w - dv.w * invsc;
    }
#pragma unroll
    for (int t = 0; t < 8; t++) mx = fmaxf(mx, v[t]);
    __shared__ float sh[8];
    __shared__ float bc;
    int lane = threadIdx.x & 31, wid = threadIdx.x >> 5;
    float wm = warpRedMax(mx);
    if (lane == 0) sh[wid] = wm;
    __syncthreads();
    if (wid == 0) {
        float t = (lane < 8) ? sh[lane] : -1e30f;
        t = warpRedMax(t);
        if (lane == 0) bc = t;
    }
    __syncthreads();
    mx = bc;
    float sum = 0.0f;
#pragma unroll
    for (int t = 0; t < 8; t++) {
        v[t] = __expf(v[t] - mx);
        sum += v[t];
    }
    __syncthreads();
    float ws = warpRedSum(sum);
    if (lane == 0) sh[wid] = ws;
    __syncthreads();
    if (wid == 0) {
        float t = (lane < 8) ? sh[lane] : 0.0f;
        t = warpRedSum(t);
        if (lane == 0) bc = t;
    }
    __syncthreads();
    const float inv = 1.0f / bc;
    const size_t pbase = (size_t)row * 1024 + threadIdx.x * 4;
#pragma unroll
    for (int p = 0; p < 4; p++) {
        uint32_t hh, ll;
        split2(v[2 * p] * inv, v[2 * p + 1] * inv, hh, ll);
        g_pH[pbase + p] = hh; g_pL[pbase + p] = ll;
    }
}

// ---------------- launch ----------------
extern "C" void kernel_launch(void* const* d_in, const int* in_sizes, int n_in,
                              void* d_out, int out_size) {
    const float* q_fp  = (const float*)d_in[0];
    const float* v_ret = (const float*)d_in[1];
    const float* pi    = (const float*)d_in[2];
    const float* Wqs = (const float*)d_in[3];  const float* bqs = (const float*)d_in[4];
    const float* Wks = (const float*)d_in[5];  const float* bks = (const float*)d_in[6];
    const float* Wvs = (const float*)d_in[7];  const float* bvs = (const float*)d_in[8];
    const float* Wqe = (const float*)d_in[9];  const float* bqe = (const float*)d_in[10];
    const float* Wke = (const float*)d_in[11]; const float* bke = (const float*)d_in[12];
    const float* Wve = (const float*)d_in[13]; const float* bve = (const float*)d_in[14];
    const float* W1  = (const float*)d_in[15]; const float* b1  = (const float*)d_in[16];
    const float* W2  = (const float*)d_in[17]; const float* b2  = (const float*)d_in[18];
    const float* gamma = (const float*)d_in[19];
    const float* ew    = (const float*)d_in[20];
    float* out = (float*)d_out;

    uint32_t *qfH, *qfL, *vrH, *vrL, *wH, *wL;
    uint32_t *qsH, *qsL, *qeH, *qeL, *ksH, *ksL, *keH, *keL;
    uint32_t *vsTH, *vsTL, *veTH, *veTL, *fH, *fL, *hH, *hL;
    float *vs_p, *ve_p, *q2_p, *k2_p;
    cudaGetSymbolAddress((void**)&qfH, g_qfH); cudaGetSymbolAddress((void**)&qfL, g_qfL);
    cudaGetSymbolAddress((void**)&vrH, g_vrH); cudaGetSymbolAddress((void**)&vrL, g_vrL);
    cudaGetSymbolAddress((void**)&wH, g_wH);   cudaGetSymbolAddress((void**)&wL, g_wL);
    cudaGetSymbolAddress((void**)&qsH, g_qsH); cudaGetSymbolAddress((void**)&qsL, g_qsL);
    cudaGetSymbolAddress((void**)&qeH, g_qeH); cudaGetSymbolAddress((void**)&qeL, g_qeL);
    cudaGetSymbolAddress((void**)&ksH, g_ksH); cudaGetSymbolAddress((void**)&ksL, g_ksL);
    cudaGetSymbolAddress((void**)&keH, g_keH); cudaGetSymbolAddress((void**)&keL, g_keL);
    cudaGetSymbolAddress((void**)&vsTH, g_vsTH); cudaGetSymbolAddress((void**)&vsTL, g_vsTL);
    cudaGetSymbolAddress((void**)&veTH, g_veTH); cudaGetSymbolAddress((void**)&veTL, g_veTL);
    cudaGetSymbolAddress((void**)&fH, g_fH);   cudaGetSymbolAddress((void**)&fL, g_fL);
    cudaGetSymbolAddress((void**)&hH, g_hH);   cudaGetSymbolAddress((void**)&hL, g_hL);
    cudaGetSymbolAddress((void**)&vs_p, g_vs); cudaGetSymbolAddress((void**)&ve_p, g_ve);
    cudaGetSymbolAddress((void**)&q2_p, g_q2); cudaGetSymbolAddress((void**)&k2_p, g_k2);

    const int GEMM_SMEM  = 20480 * 4;                 // 81920 B
    const int LOGIT_SMEM = 18432 * 4;                 // 73728 B
    const int CTX_SMEM   = 20480 * 4;                 // 81920 B
    cudaFuncSetAttribute(gemmP_kernel,   cudaFuncAttributeMaxDynamicSharedMemorySize, GEMM_SMEM);
    cudaFuncSetAttribute(logitsP_kernel, cudaFuncAttributeMaxDynamicSharedMemorySize, LOGIT_SMEM);
    cudaFuncSetAttribute(ctxP_kernel,    cudaFuncAttributeMaxDynamicSharedMemorySize, CTX_SMEM);

    // ---- pack inputs & weights ----
    pack_rows_kernel<<<(Bb*Nn*DIN/2 + 255)/256, 256>>>(q_fp,  qfH, qfL, Bb*Nn*DIN/2);
    pack_rows_kernel<<<(Bb*Mm*DIN/2 + 255)/256, 256>>>(v_ret, vrH, vrL, Bb*Mm*DIN/2);
    uint32_t* wHo[8] = {wH, wH+65536, wH+131072, wH+196608, wH+262144, wH+327680,
                        wH+393216, wH+524288};
    uint32_t* wLo[8] = {wL, wL+65536, wL+131072, wL+196608, wL+262144, wL+327680,
                        wL+393216, wL+524288};
    const float* Ws[8] = {Wqs, Wks, Wvs, Wqe, Wke, Wve, W1, W2};
    const int   Kps[8] = {256, 256, 256, 256, 256, 256, 512, 128};
    for (int w = 0; w < 8; w++)
        pack_weight_kernel<<<(Kps[w]*256 + 255)/256, 256>>>(Ws[w], wHo[w], wLo[w], Kps[w], 256);

    // ---- projections ----
    dim3 gp(2, (Bb * Nn) / 128);
    gemmP_kernel<<<gp, 256, GEMM_SMEM>>>(qfH, qfL, wHo[0], wLo[0], bqs, nullptr, qsH, qsL, 256, 256, 0, 1);
    gemmP_kernel<<<gp, 256, GEMM_SMEM>>>(vrH, vrL, wHo[1], wLo[1], bks, nullptr, ksH, ksL, 256, 256, 0, 1);
    gemmP_kernel<<<gp, 256, GEMM_SMEM>>>(vrH, vrL, wHo[2], wLo[2], bvs, vs_p, nullptr, nullptr, 256, 256, 0, 0);
    gemmP_kernel<<<gp, 256, GEMM_SMEM>>>(qfH, qfL, wHo[3], wLo[3], bqe, nullptr, qeH, qeL, 256, 256, 0, 1);
    gemmP_kernel<<<gp, 256, GEMM_SMEM>>>(vrH, vrL, wHo[4], wLo[4], bke, nullptr, keH, keL, 256, 256, 0, 1);
    gemmP_kernel<<<gp, 256, GEMM_SMEM>>>(vrH, vrL, wHo[5], wLo[5], bve, ve_p, nullptr, nullptr, 256, 256, 0, 0);

    dim3 gt(Mm / 64, Hh / 32, Bb);
    transpose_pack_kernel<<<gt, 256>>>(vs_p, vsTH, vsTL);
    transpose_pack_kernel<<<gt, 256>>>(ve_p, veTH, veTL);

    rowsumsq_kernel<<<Bb * Nn, 128>>>(qeH, qeL, q2_p);
    rowsumsq_kernel<<<Bb * Mm, 128>>>(keH, keL, k2_p);

    zero_dsum_kernel<<<1, 32>>>();
    dim3 gl(Mm / 64, Nn / 128, Bb);
    logitsP_kernel<<<gl, 256, LOGIT_SMEM>>>(pi, gamma);
    finalize_scale_kernel<<<1, 32>>>();

    softmax_kernel<<<Bb * Nn, 256>>>(ew);

    dim3 gc(Hh / 64, Nn / 128, Bb);
    ctxP_kernel<<<gc, 256, CTX_SMEM>>>();

    // ---- MLP ----
    dim3 gm(2, (Bb * Nn) / 128);
    gemmP_kernel<<<gm, 256, GEMM_SMEM>>>(fH, fL, wHo[6], wLo[6], b1, nullptr, hH, hL, 512, 256, 1, 1);
    gemmP_kernel<<<gm, 256, GEMM_SMEM>>>(hH, hL, wHo[7], wLo[7], b2, out, nullptr, nullptr, 128, 256, 0, 0);
}

// round 7
// speedup vs baseline: 1.1793x; 1.1793x over previous
#include <cuda_runtime.h>
#include <cuda_bf16.h>
#include <cstdint>

#define Bb 8
#define Nn 2048
#define Mm 2048
#define DIN 512
#define Hh 256

// ---------------- scratch (device globals; no allocs allowed) ----------------
// inputs packed: uint2{H,L} per k-pair
__device__ uint2 g_qf2[(size_t)Bb*Nn*(DIN/2)];
__device__ uint2 g_vr2[(size_t)Bb*Mm*(DIN/2)];
// weights packed n-major uint2{H,L}: [n][kp]
__device__ uint2 g_w2[6*65536 + 131072 + 32768];
// projections interleaved: uint4{qsH,qsL,qeH,qeL} / {ksH,ksL,keH,keL}, [row][128]
__device__ uint4 g_q4[(size_t)Bb*Nn*128];
__device__ uint4 g_k4[(size_t)Bb*Mm*128];
// V fp32 then transposed interleaved: uint4{vsH,vsL,veH,veL} [b][h][mp]
__device__ float g_vs[(size_t)Bb*Mm*Hh], g_ve[(size_t)Bb*Mm*Hh];
__device__ uint4 g_vT4[(size_t)Bb*Hh*1024];
// logits / dist fp32; probs packed uint2{H,L}
__device__ float g_L[(size_t)Bb*Nn*Mm];
__device__ float g_D[(size_t)Bb*Nn*Mm];
__device__ uint2 g_p2[(size_t)Bb*Nn*1024];
// fused / hidden packed uint2{H,L}
__device__ uint2 g_f2[(size_t)Bb*Nn*512];
__device__ uint2 g_h2[(size_t)Bb*Nn*128];
__device__ float g_q2[Bb*Nn], g_k2[Bb*Mm], g_dsum[Bb], g_scale[Bb];

// ---------------- helpers ----------------
__device__ __forceinline__ void split2(float f0, float f1, uint32_t& H, uint32_t& L) {
    __nv_bfloat16 h0 = __float2bfloat16(f0);
    __nv_bfloat16 h1 = __float2bfloat16(f1);
    __nv_bfloat16 l0 = __float2bfloat16(f0 - __bfloat162float(h0));
    __nv_bfloat16 l1 = __float2bfloat16(f1 - __bfloat162float(h1));
    H = (uint32_t)__bfloat16_as_ushort(h0) | ((uint32_t)__bfloat16_as_ushort(h1) << 16);
    L = (uint32_t)__bfloat16_as_ushort(l0) | ((uint32_t)__bfloat16_as_ushort(l1) << 16);
}
__device__ __forceinline__ float bflo(uint32_t u) {
    return __bfloat162float(__ushort_as_bfloat16((unsigned short)(u & 0xffff)));
}
__device__ __forceinline__ float bfhi(uint32_t u) {
    return __bfloat162float(__ushort_as_bfloat16((unsigned short)(u >> 16)));
}
__device__ __forceinline__ void mmabf(float* d, const uint32_t* a, uint32_t b0, uint32_t b1) {
    asm volatile(
        "mma.sync.aligned.m16n8k16.row.col.f32.bf16.bf16.f32 "
        "{%0,%1,%2,%3}, {%4,%5,%6,%7}, {%8,%9}, {%0,%1,%2,%3};\n"
        : "+f"(d[0]), "+f"(d[1]), "+f"(d[2]), "+f"(d[3])
        : "r"(a[0]), "r"(a[1]), "r"(a[2]), "r"(a[3]), "r"(b0), "r"(b1));
}
__device__ __forceinline__ void cpa16(void* smem, const void* gmem) {
    uint32_t s = (uint32_t)__cvta_generic_to_shared(smem);
    asm volatile("cp.async.cg.shared.global [%0], [%1], 16;\n" :: "r"(s), "l"(gmem));
}
#define CP_COMMIT() asm volatile("cp.async.commit_group;\n")
#define CP_WAIT1()  asm volatile("cp.async.wait_group 1;\n")
#define CP_WAIT0()  asm volatile("cp.async.wait_group 0;\n")

__device__ __forceinline__ float warpRedSum(float v) {
#pragma unroll
    for (int o = 16; o > 0; o >>= 1) v += __shfl_xor_sync(0xffffffffu, v, o);
    return v;
}
__device__ __forceinline__ float warpRedMax(float v) {
#pragma unroll
    for (int o = 16; o > 0; o >>= 1) v = fmaxf(v, __shfl_xor_sync(0xffffffffu, v, o));
    return v;
}

// ---------------- prep kernels ----------------
__global__ void pack_rows_kernel(const float* __restrict__ src,
                                 uint2* __restrict__ dst, int npairs) {
    int i = blockIdx.x * 256 + threadIdx.x;
    if (i >= npairs) return;
    float2 f = ((const float2*)src)[i];
    uint32_t h, l; split2(f.x, f.y, h, l);
    dst[i] = make_uint2(h, l);
}
// weights -> n-major uint2 [n][kp]
__global__ void pack_weight_kernel(const float* __restrict__ W,
                                   uint2* __restrict__ dst, int Kp, int Nc) {
    int i = blockIdx.x * 256 + threadIdx.x;
    if (i >= Kp * Nc) return;
    int n = i / Kp, kp = i - n * Kp;
    float f0 = W[(size_t)(2 * kp) * Nc + n];
    float f1 = W[(size_t)(2 * kp + 1) * Nc + n];
    uint32_t h, l; split2(f0, f1, h, l);
    dst[i] = make_uint2(h, l);
}
// Vs,Ve [b][m][h] fp32 -> uint4{vsH,vsL,veH,veL} [b][h][mp]
__global__ void transpose_pack2_kernel(const float* __restrict__ Vs,
                                       const float* __restrict__ Ve,
                                       uint4* __restrict__ T4) {
    __shared__ float ts[64][33], te[64][33];
    const int b = blockIdx.z, m0 = blockIdx.x * 64, h0 = blockIdx.y * 32;
    const int tid = threadIdx.x;
#pragma unroll
    for (int it = 0; it < 2; it++) {
        int i = tid + it * 256;
        int m = i >> 3, h4 = (i & 7) * 4;
        size_t off = ((size_t)b * Mm + m0 + m) * Hh + h0 + h4;
        float4 v = *(const float4*)&Vs[off];
        ts[m][h4 + 0] = v.x; ts[m][h4 + 1] = v.y; ts[m][h4 + 2] = v.z; ts[m][h4 + 3] = v.w;
        v = *(const float4*)&Ve[off];
        te[m][h4 + 0] = v.x; te[m][h4 + 1] = v.y; te[m][h4 + 2] = v.z; te[m][h4 + 3] = v.w;
    }
    __syncthreads();
#pragma unroll
    for (int u = 0; u < 4; u++) {
        int i = tid + u * 256;
        int h = i >> 5, mp = i & 31;
        uint32_t sh, sl, eh, el;
        split2(ts[2 * mp][h], ts[2 * mp + 1][h], sh, sl);
        split2(te[2 * mp][h], te[2 * mp + 1][h], eh, el);
        T4[((size_t)b * Hh + h0 + h) * 1024 + (m0 >> 1) + mp] = make_uint4(sh, sl, eh, el);
    }
}
// row sum of squares of the "e" plane (components z,w of uint4), 128 thr
__global__ void rowsumsq_kernel(const uint4* __restrict__ P4, float* __restrict__ dst) {
    const int row = blockIdx.x, tid = threadIdx.x;
    uint4 q = P4[(size_t)row * 128 + tid];
    float v0 = bflo(q.z) + bflo(q.w), v1 = bfhi(q.z) + bfhi(q.w);
    float s = v0 * v0 + v1 * v1;
    __shared__ float sh[4];
    int lane = tid & 31, wid = tid >> 5;
    float w = warpRedSum(s);
    if (lane == 0) sh[wid] = w;
    __syncthreads();
    if (wid == 0) {
        float t = (lane < 4) ? sh[lane] : 0.0f;
        t = warpRedSum(t);
        if (lane == 0) dst[row] = t;
    }
}
__global__ void zero_dsum_kernel() { if (threadIdx.x < Bb) g_dsum[threadIdx.x] = 0.0f; }
__global__ void finalize_scale_kernel() {
    if (threadIdx.x < Bb)
        g_scale[threadIdx.x] = fmaxf(g_dsum[threadIdx.x] * (1.0f / ((float)Nn * (float)Mm)), 1e-4f);
}

// =============================================================================
// Packed bf16x3 GEMM, interleaved uint2 planes. Tile 128x128, BK=32 (16 kp),
// 2-stage cp.async, 8 warps (4x2), warp 32x64. smem stride 20 uint2/row.
// packed out: u32 components {H,L} at base + idx*ostride.
// =============================================================================
__global__ __launch_bounds__(256, 2) void gemmP_kernel(
    const uint2* __restrict__ a2, const uint2* __restrict__ w2,
    const float* __restrict__ bias,
    float* __restrict__ outF, uint32_t* __restrict__ outP, int ostride,
    int Kp, int Nc, int act)
{
    extern __shared__ uint32_t smu[];
    uint2* smA = (uint2*)smu;        // [2][128][20]
    uint2* smB = smA + 5120;         // [2][128][20]

    const int row0 = blockIdx.y * 128;
    const int col0 = blockIdx.x * 128;
    const int tid  = threadIdx.x;
    const int lane = tid & 31, warp = tid >> 5;
    const int wR = warp >> 1, wC = warp & 1;

    float acc[2][8][4] = {};
    const int nk = Kp / 16;

    {   // prologue stage 0
#pragma unroll
        for (int it = 0; it < 4; it++) {
            int i = tid + it * 256;          // 0..1023
            int r = i >> 3, c2 = (i & 7) * 2;
            cpa16(&smA[(size_t)r * 20 + c2], a2 + (size_t)(row0 + r) * Kp + c2);
            cpa16(&smB[(size_t)r * 20 + c2], w2 + (size_t)(col0 + r) * Kp + c2);
        }
        CP_COMMIT();
    }

    for (int kt = 0; kt < nk; kt++) {
        const int s = kt & 1;
        if (kt + 1 < nk) {
            const int sn = s ^ 1;
            const int k0 = (kt + 1) * 16;
#pragma unroll
            for (int it = 0; it < 4; it++) {
                int i = tid + it * 256;
                int r = i >> 3, c2 = (i & 7) * 2;
                cpa16(&smA[(size_t)(sn * 128 + r) * 20 + c2],
                      a2 + (size_t)(row0 + r) * Kp + k0 + c2);
                cpa16(&smB[(size_t)(sn * 128 + r) * 20 + c2],
                      w2 + (size_t)(col0 + r) * Kp + k0 + c2);
            }
            CP_COMMIT();
            CP_WAIT1();
        } else {
            CP_WAIT0();
        }
        __syncthreads();
#pragma unroll
        for (int ks = 0; ks < 2; ks++) {
            const int kk = ks * 8 + (lane & 3);
            uint32_t ah[2][4], al[2][4];
#pragma unroll
            for (int i = 0; i < 2; i++) {
                int m = s * 128 + wR * 32 + i * 16 + (lane >> 2);
                uint2 p0 = smA[(size_t)m * 20 + kk];
                uint2 p1 = smA[(size_t)(m + 8) * 20 + kk];
                uint2 p2 = smA[(size_t)m * 20 + kk + 4];
                uint2 p3 = smA[(size_t)(m + 8) * 20 + kk + 4];
                ah[i][0] = p0.x; ah[i][1] = p1.x; ah[i][2] = p2.x; ah[i][3] = p3.x;
                al[i][0] = p0.y; al[i][1] = p1.y; al[i][2] = p2.y; al[i][3] = p3.y;
            }
#pragma unroll
            for (int j = 0; j < 8; j++) {
                int n = s * 128 + wC * 64 + j * 8 + (lane >> 2);
                uint2 b0 = smB[(size_t)n * 20 + kk];
                uint2 b1 = smB[(size_t)n * 20 + kk + 4];
#pragma unroll
                for (int i = 0; i < 2; i++) {
                    mmabf(acc[i][j], ah[i], b0.x, b1.x);
                    mmabf(acc[i][j], ah[i], b0.y, b1.y);
                    mmabf(acc[i][j], al[i], b0.x, b1.x);
                }
            }
        }
        __syncthreads();
    }
#pragma unroll
    for (int i = 0; i < 2; i++) {
        int r = row0 + wR * 32 + i * 16 + (lane >> 2);
#pragma unroll
        for (int j = 0; j < 8; j++) {
            int c = col0 + wC * 64 + j * 8 + 2 * (lane & 3);
            float b0 = bias[c], b1 = bias[c + 1];
            float v0 = acc[i][j][0] + b0, v1 = acc[i][j][1] + b1;
            float v2 = acc[i][j][2] + b0, v3 = acc[i][j][3] + b1;
            if (act) {
                v0 = v0 / (1.0f + __expf(-v0));
                v1 = v1 / (1.0f + __expf(-v1));
                v2 = v2 / (1.0f + __expf(-v2));
                v3 = v3 / (1.0f + __expf(-v3));
            }
            if (outP) {
                uint32_t hh, ll;
                size_t o0 = ((size_t)r * (Nc >> 1) + (c >> 1)) * ostride;
                split2(v0, v1, hh, ll); *(uint2*)&outP[o0] = make_uint2(hh, ll);
                size_t o1 = ((size_t)(r + 8) * (Nc >> 1) + (c >> 1)) * ostride;
                split2(v2, v3, hh, ll); *(uint2*)&outP[o1] = make_uint2(hh, ll);
            } else {
                *(float2*)&outF[(size_t)r * Nc + c]       = make_float2(v0, v1);
                *(float2*)&outF[(size_t)(r + 8) * Nc + c] = make_float2(v2, v3);
            }
        }
    }
}

// =============================================================================
// Logits: dual bf16x3 NT GEMM from interleaved uint4 planes.
// Block 128(n) x 64(m), BK=16 (8 kp/stage), 2-stage cp.async, 73728B smem.
// smem stride 12 uint4/row.
// =============================================================================
__global__ __launch_bounds__(256, 2) void logitsP_kernel(
    const float* __restrict__ pi_star, const float* __restrict__ gamma_p)
{
    extern __shared__ uint32_t smu[];
    uint4* smQ = (uint4*)smu;        // [2][128][12]
    uint4* smK = smQ + 3072;         // [2][64][12]

    const int b  = blockIdx.z;
    const int n0 = blockIdx.y * 128;
    const int m0 = blockIdx.x * 64;
    const int tid = threadIdx.x;
    const int lane = tid & 31, warp = tid >> 5;
    const int wR = warp >> 1, wC = warp & 1;

    const uint4* q4 = g_q4 + (size_t)(b * Nn + n0) * 128;
    const uint4* k4 = g_k4 + (size_t)(b * Mm + m0) * 128;

    float accS[2][4][4] = {}, accE[2][4][4] = {};
    const int nk = 16;   // 128 kp / 8

    {   // prologue
#pragma unroll
        for (int it = 0; it < 4; it++) {
            int i = tid + it * 256;          // 0..1023
            int r = i >> 3, kp = i & 7;
            cpa16(&smQ[(size_t)r * 12 + kp], q4 + (size_t)r * 128 + kp);
        }
#pragma unroll
        for (int it = 0; it < 2; it++) {
            int i = tid + it * 256;          // 0..511
            int r = i >> 3, kp = i & 7;
            cpa16(&smK[(size_t)r * 12 + kp], k4 + (size_t)r * 128 + kp);
        }
        CP_COMMIT();
    }

    for (int kt = 0; kt < nk; kt++) {
        const int s = kt & 1;
        if (kt + 1 < nk) {
            const int sn = s ^ 1;
            const int k0 = (kt + 1) * 8;
#pragma unroll
            for (int it = 0; it < 4; it++) {
                int i = tid + it * 256;
                int r = i >> 3, kp = i & 7;
                cpa16(&smQ[(size_t)(sn * 128 + r) * 12 + kp], q4 + (size_t)r * 128 + k0 + kp);
            }
#pragma unroll
            for (int it = 0; it < 2; it++) {
                int i = tid + it * 256;
                int r = i >> 3, kp = i & 7;
                cpa16(&smK[(size_t)(sn * 64 + r) * 12 + kp], k4 + (size_t)r * 128 + k0 + kp);
            }
            CP_COMMIT();
            CP_WAIT1();
        } else {
            CP_WAIT0();
        }
        __syncthreads();

        const int kk = lane & 3;
        uint32_t ash[2][4], asl[2][4], aeh[2][4], ael[2][4];
#pragma unroll
        for (int i = 0; i < 2; i++) {
            int m = s * 128 + wR * 32 + i * 16 + (lane >> 2);
            uint4 p0 = smQ[(size_t)m * 12 + kk];
            uint4 p1 = smQ[(size_t)(m + 8) * 12 + kk];
            uint4 p2 = smQ[(size_t)m * 12 + kk + 4];
            uint4 p3 = smQ[(size_t)(m + 8) * 12 + kk + 4];
            ash[i][0] = p0.x; ash[i][1] = p1.x; ash[i][2] = p2.x; ash[i][3] = p3.x;
            asl[i][0] = p0.y; asl[i][1] = p1.y; asl[i][2] = p2.y; asl[i][3] = p3.y;
            aeh[i][0] = p0.z; aeh[i][1] = p1.z; aeh[i][2] = p2.z; aeh[i][3] = p3.z;
            ael[i][0] = p0.w; ael[i][1] = p1.w; ael[i][2] = p2.w; ael[i][3] = p3.w;
        }
#pragma unroll
        for (int j = 0; j < 4; j++) {
            int n = s * 64 + wC * 32 + j * 8 + (lane >> 2);
            uint4 k0v = smK[(size_t)n * 12 + kk];
            uint4 k1v = smK[(size_t)n * 12 + kk + 4];
#pragma unroll
            for (int i = 0; i < 2; i++) {
                mmabf(accS[i][j], ash[i], k0v.x, k1v.x);
                mmabf(accS[i][j], ash[i], k0v.y, k1v.y);
                mmabf(accS[i][j], asl[i], k0v.x, k1v.x);
                mmabf(accE[i][j], aeh[i], k0v.z, k1v.z);
                mmabf(accE[i][j], aeh[i], k0v.w, k1v.w);
                mmabf(accE[i][j], ael[i], k0v.z, k1v.z);
            }
        }
        __syncthreads();
    }

    const float g = gamma_p[0];
    float sumd = 0.0f;
#pragma unroll
    for (int i = 0; i < 2; i++) {
        int n_lo = n0 + wR * 32 + i * 16 + (lane >> 2);
        float q2a = g_q2[b * Nn + n_lo];
        float q2b = g_q2[b * Nn + n_lo + 8];
#pragma unroll
        for (int j = 0; j < 4; j++) {
            int m = m0 + wC * 32 + j * 8 + 2 * (lane & 3);
            float k2a = g_k2[b * Mm + m], k2b = g_k2[b * Mm + m + 1];
            size_t base0 = ((size_t)b * Nn + n_lo) * Mm + m;
            float2 piv = *(const float2*)&pi_star[base0];
            float d0 = sqrtf(fmaxf(q2a + k2a - 2.0f * accE[i][j][0], 1e-12f));
            float d1 = sqrtf(fmaxf(q2a + k2b - 2.0f * accE[i][j][1], 1e-12f));
            sumd += d0 + d1;
            *(float2*)&g_D[base0] = make_float2(d0, d1);
            float L0 = accS[i][j][0] * 0.0625f + g * __logf(fmaxf(piv.x, 1e-9f));
            float L1 = accS[i][j][1] * 0.0625f + g * __logf(fmaxf(piv.y, 1e-9f));
            *(float2*)&g_L[base0] = make_float2(L0, L1);
            size_t base1 = ((size_t)b * Nn + n_lo + 8) * Mm + m;
            piv = *(const float2*)&pi_star[base1];
            float d2v = sqrtf(fmaxf(q2b + k2a - 2.0f * accE[i][j][2], 1e-12f));
            float d3v = sqrtf(fmaxf(q2b + k2b - 2.0f * accE[i][j][3], 1e-12f));
            sumd += d2v + d3v;
            *(float2*)&g_D[base1] = make_float2(d2v, d3v);
            float L2 = accS[i][j][2] * 0.0625f + g * __logf(fmaxf(piv.x, 1e-9f));
            float L3 = accS[i][j][3] * 0.0625f + g * __logf(fmaxf(piv.y, 1e-9f));
            *(float2*)&g_L[base1] = make_float2(L2, L3);
        }
    }
    float* red = (float*)smu;
    red[tid] = sumd;
    __syncthreads();
    for (int sred = 128; sred > 0; sred >>= 1) {
        if (tid < sred) red[tid] += red[tid + sred];
        __syncthreads();
    }
    if (tid == 0) atomicAdd(&g_dsum[b], red[0]);
}

// =============================================================================
// Ctx: dual bf16x3 NN GEMM probs@Vs / probs@Ve from interleaved planes.
// Block 128(n) x 64(h), BK=32 (16 kp/stage), 2-stage cp.async, 81920B smem.
// P: uint2 stride 20; V: uint4 stride 20.
// =============================================================================
__global__ __launch_bounds__(256, 2) void ctxP_kernel()
{
    extern __shared__ uint32_t smu[];
    uint2* smP = (uint2*)smu;                // [2][128][20] uint2 = 40960 B
    uint4* smV = (uint4*)(smu + 10240);      // [2][64][20] uint4 = 40960 B

    const int b  = blockIdx.z;
    const int n0 = blockIdx.y * 128;
    const int h0 = blockIdx.x * 64;
    const int tid = threadIdx.x;
    const int lane = tid & 31, warp = tid >> 5;
    const int wR = warp >> 1, wC = warp & 1;

    const uint2* p2 = g_p2 + (size_t)(b * Nn + n0) * 1024;
    const uint4* v4 = g_vT4 + ((size_t)b * Hh + h0) * 1024;

    float accS[2][4][4] = {}, accE[2][4][4] = {};
    const int nk = 64;   // 1024 mp / 16

    {   // prologue
#pragma unroll
        for (int it = 0; it < 4; it++) {
            int i = tid + it * 256;          // 0..1023
            int r = i >> 3, c2 = (i & 7) * 2;
            cpa16(&smP[(size_t)r * 20 + c2], p2 + (size_t)r * 1024 + c2);
            int rv = i >> 4, kp = i & 15;
            cpa16(&smV[(size_t)rv * 20 + kp], v4 + (size_t)rv * 1024 + kp);
        }
        CP_COMMIT();
    }

    for (int kt = 0; kt < nk; kt++) {
        const int s = kt & 1;
        if (kt + 1 < nk) {
            const int sn = s ^ 1;
            const int mp0 = (kt + 1) * 16;
#pragma unroll
            for (int it = 0; it < 4; it++) {
                int i = tid + it * 256;
                int r = i >> 3, c2 = (i & 7) * 2;
                cpa16(&smP[(size_t)(sn * 128 + r) * 20 + c2],
                      p2 + (size_t)r * 1024 + mp0 + c2);
                int rv = i >> 4, kp = i & 15;
                cpa16(&smV[(size_t)(sn * 64 + rv) * 20 + kp],
                      v4 + (size_t)rv * 1024 + mp0 + kp);
            }
            CP_COMMIT();
            CP_WAIT1();
        } else {
            CP_WAIT0();
        }
        __syncthreads();
#pragma unroll
        for (int ks = 0; ks < 2; ks++) {
            const int kk = ks * 8 + (lane & 3);
            uint32_t ph[2][4], pl[2][4];
#pragma unroll
            for (int i = 0; i < 2; i++) {
                int m = s * 128 + wR * 32 + i * 16 + (lane >> 2);
                uint2 p0 = smP[(size_t)m * 20 + kk];
                uint2 p1 = smP[(size_t)(m + 8) * 20 + kk];
                uint2 p2v = smP[(size_t)m * 20 + kk + 4];
                uint2 p3 = smP[(size_t)(m + 8) * 20 + kk + 4];
                ph[i][0] = p0.x; ph[i][1] = p1.x; ph[i][2] = p2v.x; ph[i][3] = p3.x;
                pl[i][0] = p0.y; pl[i][1] = p1.y; pl[i][2] = p2v.y; pl[i][3] = p3.y;
            }
#pragma unroll
            for (int j = 0; j < 4; j++) {
                int n = s * 64 + wC * 32 + j * 8 + (lane >> 2);
                uint4 v0 = smV[(size_t)n * 20 + kk];
                uint4 v1 = smV[(size_t)n * 20 + kk + 4];
#pragma unroll
                for (int i = 0; i < 2; i++) {
                    mmabf(accS[i][j], ph[i], v0.x, v1.x);
                    mmabf(accS[i][j], ph[i], v0.y, v1.y);
                    mmabf(accS[i][j], pl[i], v0.x, v1.x);
                    mmabf(accE[i][j], ph[i], v0.z, v1.z);
                    mmabf(accE[i][j], ph[i], v0.w, v1.w);
                    mmabf(accE[i][j], pl[i], v0.z, v1.z);
                }
            }
        }
        __syncthreads();
    }
#pragma unroll
    for (int i = 0; i < 2; i++) {
        int n_lo = n0 + wR * 32 + i * 16 + (lane >> 2);
#pragma unroll
        for (int j = 0; j < 4; j++) {
            int h = h0 + wC * 32 + j * 8 + 2 * (lane & 3);
#pragma unroll
            for (int half = 0; half < 2; half++) {
                int n = n_lo + half * 8;
                float cs0 = accS[i][j][half * 2 + 0], cs1 = accS[i][j][half * 2 + 1];
                float ce0 = accE[i][j][half * 2 + 0], ce1 = accE[i][j][half * 2 + 1];
                size_t fb = ((size_t)b * Nn + n) * 512;
                uint32_t hh, ll;
                split2(cs0, cs1, hh, ll);             g_f2[fb + (h >> 1)]       = make_uint2(hh, ll);
                split2(ce0, ce1, hh, ll);             g_f2[fb + 128 + (h >> 1)] = make_uint2(hh, ll);
                split2(cs0 - ce0, cs1 - ce1, hh, ll); g_f2[fb + 256 + (h >> 1)] = make_uint2(hh, ll);
                split2(cs0 * ce0, cs1 * ce1, hh, ll); g_f2[fb + 384 + (h >> 1)] = make_uint2(hh, ll);
            }
        }
    }
}

// ---------------- softmax ----------------
__global__ void softmax_kernel(const float* __restrict__ ew_p) {
    const int row = blockIdx.x;
    const int b   = row / Nn;
    const float invsc = ew_p[0] / g_scale[b];
    const size_t base = (size_t)row * Mm;
    const int c0 = threadIdx.x * 8;
    float v[8];
    float mx = -1e30f;
#pragma unroll
    for (int q = 0; q < 2; q++) {
        float4 lv = *(const float4*)&g_L[base + c0 + q * 4];
        float4 dv = *(const float4*)&g_D[base + c0 + q * 4];
        v[q*4+0] = lv.x - dv.x * invsc; v[q*4+1] = lv.y - dv.y * invsc;
        v[q*4+2] = lv.z - dv.z * invsc; v[q*4+3] = lv.w - dv.w * invsc;
    }
#pragma unroll
    for (int t = 0; t < 8; t++) mx = fmaxf(mx, v[t]);
    __shared__ float sh[8];
    __shared__ float bc;
    int lane = threadIdx.x & 31, wid = threadIdx.x >> 5;
    float wm = warpRedMax(mx);
    if (lane == 0) sh[wid] = wm;
    __syncthreads();
    if (wid == 0) {
        float t = (lane < 8) ? sh[lane] : -1e30f;
        t = warpRedMax(t);
        if (lane == 0) bc = t;
    }
    __syncthreads();
    mx = bc;
    float sum = 0.0f;
#pragma unroll
    for (int t = 0; t < 8; t++) {
        v[t] = __expf(v[t] - mx);
        sum += v[t];
    }
    __syncthreads();
    float ws = warpRedSum(sum);
    if (lane == 0) sh[wid] = ws;
    __syncthreads();
    if (wid == 0) {
        float t = (lane < 8) ? sh[lane] : 0.0f;
        t = warpRedSum(t);
        if (lane == 0) bc = t;
    }
    __syncthreads();
    const float inv = 1.0f / bc;
    const size_t pbase = (size_t)row * 1024 + threadIdx.x * 4;
#pragma unroll
    for (int p = 0; p < 4; p++) {
        uint32_t hh, ll;
        split2(v[2 * p] * inv, v[2 * p + 1] * inv, hh, ll);
        g_p2[pbase + p] = make_uint2(hh, ll);
    }
}

// ---------------- launch ----------------
extern "C" void kernel_launch(void* const* d_in, const int* in_sizes, int n_in,
                              void* d_out, int out_size) {
    const float* q_fp  = (const float*)d_in[0];
    const float* v_ret = (const float*)d_in[1];
    const float* pi    = (const float*)d_in[2];
    const float* Wqs = (const float*)d_in[3];  const float* bqs = (const float*)d_in[4];
    const float* Wks = (const float*)d_in[5];  const float* bks = (const float*)d_in[6];
    const float* Wvs = (const float*)d_in[7];  const float* bvs = (const float*)d_in[8];
    const float* Wqe = (const float*)d_in[9];  const float* bqe = (const float*)d_in[10];
    const float* Wke = (const float*)d_in[11]; const float* bke = (const float*)d_in[12];
    const float* Wve = (const float*)d_in[13]; const float* bve = (const float*)d_in[14];
    const float* W1  = (const float*)d_in[15]; const float* b1  = (const float*)d_in[16];
    const float* W2  = (const float*)d_in[17]; const float* b2  = (const float*)d_in[18];
    const float* gamma = (const float*)d_in[19];
    const float* ew    = (const float*)d_in[20];
    float* out = (float*)d_out;

    uint2 *qf2, *vr2, *w2, *f2, *h2;
    uint4 *q4, *k4, *vT4;
    float *vs_p, *ve_p, *q2_p, *k2_p;
    cudaGetSymbolAddress((void**)&qf2, g_qf2);
    cudaGetSymbolAddress((void**)&vr2, g_vr2);
    cudaGetSymbolAddress((void**)&w2, g_w2);
    cudaGetSymbolAddress((void**)&q4, g_q4);
    cudaGetSymbolAddress((void**)&k4, g_k4);
    cudaGetSymbolAddress((void**)&vT4, g_vT4);
    cudaGetSymbolAddress((void**)&f2, g_f2);
    cudaGetSymbolAddress((void**)&h2, g_h2);
    cudaGetSymbolAddress((void**)&vs_p, g_vs);
    cudaGetSymbolAddress((void**)&ve_p, g_ve);
    cudaGetSymbolAddress((void**)&q2_p, g_q2);
    cudaGetSymbolAddress((void**)&k2_p, g_k2);

    const int GEMM_SMEM  = 81920;
    const int LOGIT_SMEM = 73728;
    const int CTX_SMEM   = 81920;
    cudaFuncSetAttribute(gemmP_kernel,   cudaFuncAttributeMaxDynamicSharedMemorySize, GEMM_SMEM);
    cudaFuncSetAttribute(logitsP_kernel, cudaFuncAttributeMaxDynamicSharedMemorySize, LOGIT_SMEM);
    cudaFuncSetAttribute(ctxP_kernel,    cudaFuncAttributeMaxDynamicSharedMemorySize, CTX_SMEM);

    // ---- pack inputs & weights ----
    pack_rows_kernel<<<(Bb*Nn*DIN/2 + 255)/256, 256>>>(q_fp,  qf2, Bb*Nn*DIN/2);
    pack_rows_kernel<<<(Bb*Mm*DIN/2 + 255)/256, 256>>>(v_ret, vr2, Bb*Mm*DIN/2);
    uint2* wo[8] = {w2, w2+65536, w2+131072, w2+196608, w2+262144, w2+327680,
                    w2+393216, w2+524288};
    const float* Ws[8] = {Wqs, Wks, Wvs, Wqe, Wke, Wve, W1, W2};
    const int   Kps[8] = {256, 256, 256, 256, 256, 256, 512, 128};
    for (int w = 0; w < 8; w++)
        pack_weight_kernel<<<(Kps[w]*256 + 255)/256, 256>>>(Ws[w], wo[w], Kps[w], 256);

    // ---- projections ----
    dim3 gp(2, (Bb * Nn) / 128);
    gemmP_kernel<<<gp, 256, GEMM_SMEM>>>(qf2, wo[0], bqs, nullptr, (uint32_t*)q4 + 0, 4, 256, 256, 0);
    gemmP_kernel<<<gp, 256, GEMM_SMEM>>>(vr2, wo[1], bks, nullptr, (uint32_t*)k4 + 0, 4, 256, 256, 0);
    gemmP_kernel<<<gp, 256, GEMM_SMEM>>>(vr2, wo[2], bvs, vs_p, nullptr, 0, 256, 256, 0);
    gemmP_kernel<<<gp, 256, GEMM_SMEM>>>(qf2, wo[3], bqe, nullptr, (uint32_t*)q4 + 2, 4, 256, 256, 0);
    gemmP_kernel<<<gp, 256, GEMM_SMEM>>>(vr2, wo[4], bke, nullptr, (uint32_t*)k4 + 2, 4, 256, 256, 0);
    gemmP_kernel<<<gp, 256, GEMM_SMEM>>>(vr2, wo[5], bve, ve_p, nullptr, 0, 256, 256, 0);

    dim3 gt(Mm / 64, Hh / 32, Bb);
    transpose_pack2_kernel<<<gt, 256>>>(vs_p, ve_p, vT4);

    rowsumsq_kernel<<<Bb * Nn, 128>>>(q4, q2_p);
    rowsumsq_kernel<<<Bb * Mm, 128>>>(k4, k2_p);

    zero_dsum_kernel<<<1, 32>>>();
    dim3 gl(Mm / 64, Nn / 128, Bb);
    logitsP_kernel<<<gl, 256, LOGIT_SMEM>>>(pi, gamma);
    finalize_scale_kernel<<<1, 32>>>();

    softmax_kernel<<<Bb * Nn, 256>>>(ew);

    dim3 gc(Hh / 64, Nn / 128, Bb);
    ctxP_kernel<<<gc, 256, CTX_SMEM>>>();

    // ---- MLP ----
    dim3 gm(2, (Bb * Nn) / 128);
    gemmP_kernel<<<gm, 256, GEMM_SMEM>>>(f2, wo[6], b1, nullptr, (uint32_t*)h2, 2, 512, 256, 1);
    gemmP_kernel<<<gm, 256, GEMM_SMEM>>>(h2, wo[7], b2, out, nullptr, 0, 128, 256, 0);
}

// round 8
// speedup vs baseline: 1.2008x; 1.0182x over previous
#include <cuda_runtime.h>
#include <cuda_bf16.h>
#include <cstdint>

#define Bb 8
#define Nn 2048
#define Mm 2048
#define DIN 512
#define Hh 256

// ---------------- scratch (device globals; no allocs allowed) ----------------
__device__ uint2 g_qf2[(size_t)Bb*Nn*(DIN/2)];
__device__ uint2 g_vr2[(size_t)Bb*Mm*(DIN/2)];
__device__ uint2 g_w2[6*65536 + 131072 + 32768];
__device__ uint4 g_q4[(size_t)Bb*Nn*128];
__device__ uint4 g_k4[(size_t)Bb*Mm*128];
__device__ float g_vs[(size_t)Bb*Mm*Hh], g_ve[(size_t)Bb*Mm*Hh];
__device__ uint4 g_vT4[(size_t)Bb*Hh*1024];
__device__ float g_L[(size_t)Bb*Nn*Mm];
__device__ float g_D[(size_t)Bb*Nn*Mm];
__device__ uint2 g_p2[(size_t)Bb*Nn*1024];
__device__ uint2 g_f2[(size_t)Bb*Nn*512];
__device__ uint2 g_h2[(size_t)Bb*Nn*128];
__device__ float g_q2[Bb*Nn], g_k2[Bb*Mm], g_dsum[Bb], g_scale[Bb];

// ---------------- helpers ----------------
__device__ __forceinline__ void split2(float f0, float f1, uint32_t& H, uint32_t& L) {
    __nv_bfloat16 h0 = __float2bfloat16(f0);
    __nv_bfloat16 h1 = __float2bfloat16(f1);
    __nv_bfloat16 l0 = __float2bfloat16(f0 - __bfloat162float(h0));
    __nv_bfloat16 l1 = __float2bfloat16(f1 - __bfloat162float(h1));
    H = (uint32_t)__bfloat16_as_ushort(h0) | ((uint32_t)__bfloat16_as_ushort(h1) << 16);
    L = (uint32_t)__bfloat16_as_ushort(l0) | ((uint32_t)__bfloat16_as_ushort(l1) << 16);
}
__device__ __forceinline__ float bflo(uint32_t u) {
    return __bfloat162float(__ushort_as_bfloat16((unsigned short)(u & 0xffff)));
}
__device__ __forceinline__ float bfhi(uint32_t u) {
    return __bfloat162float(__ushort_as_bfloat16((unsigned short)(u >> 16)));
}
__device__ __forceinline__ void mmabf(float* d, const uint32_t* a, uint32_t b0, uint32_t b1) {
    asm volatile(
        "mma.sync.aligned.m16n8k16.row.col.f32.bf16.bf16.f32 "
        "{%0,%1,%2,%3}, {%4,%5,%6,%7}, {%8,%9}, {%0,%1,%2,%3};\n"
        : "+f"(d[0]), "+f"(d[1]), "+f"(d[2]), "+f"(d[3])
        : "r"(a[0]), "r"(a[1]), "r"(a[2]), "r"(a[3]), "r"(b0), "r"(b1));
}
__device__ __forceinline__ void cpa16(void* smem, const void* gmem) {
    uint32_t s = (uint32_t)__cvta_generic_to_shared(smem);
    asm volatile("cp.async.cg.shared.global [%0], [%1], 16;\n" :: "r"(s), "l"(gmem));
}
#define CP_COMMIT() asm volatile("cp.async.commit_group;\n")
#define CP_WAIT1()  asm volatile("cp.async.wait_group 1;\n")
#define CP_WAIT0()  asm volatile("cp.async.wait_group 0;\n")

__device__ __forceinline__ float warpRedSum(float v) {
#pragma unroll
    for (int o = 16; o > 0; o >>= 1) v += __shfl_xor_sync(0xffffffffu, v, o);
    return v;
}
__device__ __forceinline__ float warpRedMax(float v) {
#pragma unroll
    for (int o = 16; o > 0; o >>= 1) v = fmaxf(v, __shfl_xor_sync(0xffffffffu, v, o));
    return v;
}

// ---------------- prep kernels ----------------
__global__ void pack_rows_kernel(const float* __restrict__ src,
                                 uint2* __restrict__ dst, int npairs) {
    int i = blockIdx.x * 256 + threadIdx.x;
    if (i >= npairs) return;
    float2 f = ((const float2*)src)[i];
    uint32_t h, l; split2(f.x, f.y, h, l);
    dst[i] = make_uint2(h, l);
}
__global__ void pack_weight_kernel(const float* __restrict__ W,
                                   uint2* __restrict__ dst, int Kp, int Nc) {
    int i = blockIdx.x * 256 + threadIdx.x;
    if (i >= Kp * Nc) return;
    int n = i / Kp, kp = i - n * Kp;
    float f0 = W[(size_t)(2 * kp) * Nc + n];
    float f1 = W[(size_t)(2 * kp + 1) * Nc + n];
    uint32_t h, l; split2(f0, f1, h, l);
    dst[i] = make_uint2(h, l);
}
__global__ void transpose_pack2_kernel(const float* __restrict__ Vs,
                                       const float* __restrict__ Ve,
                                       uint4* __restrict__ T4) {
    __shared__ float ts[64][33], te[64][33];
    const int b = blockIdx.z, m0 = blockIdx.x * 64, h0 = blockIdx.y * 32;
    const int tid = threadIdx.x;
#pragma unroll
    for (int it = 0; it < 2; it++) {
        int i = tid + it * 256;
        int m = i >> 3, h4 = (i & 7) * 4;
        size_t off = ((size_t)b * Mm + m0 + m) * Hh + h0 + h4;
        float4 v = *(const float4*)&Vs[off];
        ts[m][h4 + 0] = v.x; ts[m][h4 + 1] = v.y; ts[m][h4 + 2] = v.z; ts[m][h4 + 3] = v.w;
        v = *(const float4*)&Ve[off];
        te[m][h4 + 0] = v.x; te[m][h4 + 1] = v.y; te[m][h4 + 2] = v.z; te[m][h4 + 3] = v.w;
    }
    __syncthreads();
#pragma unroll
    for (int u = 0; u < 4; u++) {
        int i = tid + u * 256;
        int h = i >> 5, mp = i & 31;
        uint32_t sh, sl, eh, el;
        split2(ts[2 * mp][h], ts[2 * mp + 1][h], sh, sl);
        split2(te[2 * mp][h], te[2 * mp + 1][h], eh, el);
        T4[((size_t)b * Hh + h0 + h) * 1024 + (m0 >> 1) + mp] = make_uint4(sh, sl, eh, el);
    }
}
__global__ void rowsumsq_kernel(const uint4* __restrict__ P4, float* __restrict__ dst) {
    const int row = blockIdx.x, tid = threadIdx.x;
    uint4 q = P4[(size_t)row * 128 + tid];
    float v0 = bflo(q.z) + bflo(q.w), v1 = bfhi(q.z) + bfhi(q.w);
    float s = v0 * v0 + v1 * v1;
    __shared__ float sh[4];
    int lane = tid & 31, wid = tid >> 5;
    float w = warpRedSum(s);
    if (lane == 0) sh[wid] = w;
    __syncthreads();
    if (wid == 0) {
        float t = (lane < 4) ? sh[lane] : 0.0f;
        t = warpRedSum(t);
        if (lane == 0) dst[row] = t;
    }
}
__global__ void zero_dsum_kernel() { if (threadIdx.x < Bb) g_dsum[threadIdx.x] = 0.0f; }
__global__ void finalize_scale_kernel() {
    if (threadIdx.x < Bb)
        g_scale[threadIdx.x] = fmaxf(g_dsum[threadIdx.x] * (1.0f / ((float)Nn * (float)Mm)), 1e-4f);
}

// =============================================================================
// Dual-output projection GEMM: Ca = A@Wa + ba, Cb = A@Wb + bb (shared A tile).
// Block 128(row) x 64(col), BK=16 (8 kp/stage), 2-stage cp.async, 48KB smem.
// Warps 4x2, warp 32x32 per output. Out: uint4 interleave or 2x fp32.
// =============================================================================
__global__ __launch_bounds__(256, 2) void gemm2_kernel(
    const uint2* __restrict__ a2,
    const uint2* __restrict__ wa, const uint2* __restrict__ wb,
    const float* __restrict__ biasA, const float* __restrict__ biasB,
    uint4* __restrict__ out4,
    float* __restrict__ outFa, float* __restrict__ outFb,
    int Kp)
{
    extern __shared__ uint32_t smu[];
    uint2* smA  = (uint2*)smu;       // [2][128][12]
    uint2* smB1 = smA + 3072;        // [2][64][12]
    uint2* smB2 = smB1 + 1536;       // [2][64][12]

    const int row0 = blockIdx.y * 128;
    const int col0 = blockIdx.x * 64;
    const int tid  = threadIdx.x;
    const int lane = tid & 31, warp = tid >> 5;
    const int wR = warp >> 1, wC = warp & 1;

    float acc1[2][4][4] = {}, acc2[2][4][4] = {};
    const int nk = Kp / 8;

    {   // prologue
#pragma unroll
        for (int it = 0; it < 2; it++) {
            int i = tid + it * 256;          // 0..511
            int r = i >> 2, c2 = (i & 3) * 2;
            cpa16(&smA[(size_t)r * 12 + c2], a2 + (size_t)(row0 + r) * Kp + c2);
        }
        {
            int r = tid >> 2, c2 = (tid & 3) * 2;
            cpa16(&smB1[(size_t)r * 12 + c2], wa + (size_t)(col0 + r) * Kp + c2);
            cpa16(&smB2[(size_t)r * 12 + c2], wb + (size_t)(col0 + r) * Kp + c2);
        }
        CP_COMMIT();
    }

    for (int kt = 0; kt < nk; kt++) {
        const int s = kt & 1;
        if (kt + 1 < nk) {
            const int sn = s ^ 1;
            const int k0 = (kt + 1) * 8;
#pragma unroll
            for (int it = 0; it < 2; it++) {
                int i = tid + it * 256;
                int r = i >> 2, c2 = (i & 3) * 2;
                cpa16(&smA[(size_t)(sn * 128 + r) * 12 + c2],
                      a2 + (size_t)(row0 + r) * Kp + k0 + c2);
            }
            {
                int r = tid >> 2, c2 = (tid & 3) * 2;
                cpa16(&smB1[(size_t)(sn * 64 + r) * 12 + c2],
                      wa + (size_t)(col0 + r) * Kp + k0 + c2);
                cpa16(&smB2[(size_t)(sn * 64 + r) * 12 + c2],
                      wb + (size_t)(col0 + r) * Kp + k0 + c2);
            }
            CP_COMMIT();
            CP_WAIT1();
        } else {
            CP_WAIT0();
        }
        __syncthreads();

        const int kk = lane & 3;
        uint32_t ah[2][4], al[2][4];
#pragma unroll
        for (int i = 0; i < 2; i++) {
            int m = s * 128 + wR * 32 + i * 16 + (lane >> 2);
            uint2 p0 = smA[(size_t)m * 12 + kk];
            uint2 p1 = smA[(size_t)(m + 8) * 12 + kk];
            uint2 p2 = smA[(size_t)m * 12 + kk + 4];
            uint2 p3 = smA[(size_t)(m + 8) * 12 + kk + 4];
            ah[i][0] = p0.x; ah[i][1] = p1.x; ah[i][2] = p2.x; ah[i][3] = p3.x;
            al[i][0] = p0.y; al[i][1] = p1.y; al[i][2] = p2.y; al[i][3] = p3.y;
        }
#pragma unroll
        for (int j = 0; j < 4; j++) {
            int n = s * 64 + wC * 32 + j * 8 + (lane >> 2);
            uint2 b10 = smB1[(size_t)n * 12 + kk];
            uint2 b11 = smB1[(size_t)n * 12 + kk + 4];
            uint2 b20 = smB2[(size_t)n * 12 + kk];
            uint2 b21 = smB2[(size_t)n * 12 + kk + 4];
#pragma unroll
            for (int i = 0; i < 2; i++) {
                mmabf(acc1[i][j], ah[i], b10.x, b11.x);
                mmabf(acc1[i][j], ah[i], b10.y, b11.y);
                mmabf(acc1[i][j], al[i], b10.x, b11.x);
                mmabf(acc2[i][j], ah[i], b20.x, b21.x);
                mmabf(acc2[i][j], ah[i], b20.y, b21.y);
                mmabf(acc2[i][j], al[i], b20.x, b21.x);
            }
        }
        __syncthreads();
    }

#pragma unroll
    for (int i = 0; i < 2; i++) {
        int r = row0 + wR * 32 + i * 16 + (lane >> 2);
#pragma unroll
        for (int j = 0; j < 4; j++) {
            int c = col0 + wC * 32 + j * 8 + 2 * (lane & 3);
            float ba0 = biasA[c], ba1 = biasA[c + 1];
            float bb0 = biasB[c], bb1 = biasB[c + 1];
#pragma unroll
            for (int half = 0; half < 2; half++) {
                int rr = r + half * 8;
                float va0 = acc1[i][j][half * 2 + 0] + ba0;
                float va1 = acc1[i][j][half * 2 + 1] + ba1;
                float vb0 = acc2[i][j][half * 2 + 0] + bb0;
                float vb1 = acc2[i][j][half * 2 + 1] + bb1;
                if (out4) {
                    uint32_t sh, sl, eh, el;
                    split2(va0, va1, sh, sl);
                    split2(vb0, vb1, eh, el);
                    out4[(size_t)rr * 128 + (c >> 1)] = make_uint4(sh, sl, eh, el);
                } else {
                    *(float2*)&outFa[(size_t)rr * 256 + c] = make_float2(va0, va1);
                    *(float2*)&outFb[(size_t)rr * 256 + c] = make_float2(vb0, vb1);
                }
            }
        }
    }
}

// =============================================================================
// Single-output GEMM for MLP (from R7, interleaved uint2 planes).
// Tile 128x128, BK=32 (16 kp), 2-stage, warps 4x2, warp 32x64.
// =============================================================================
__global__ __launch_bounds__(256, 2) void gemmP_kernel(
    const uint2* __restrict__ a2, const uint2* __restrict__ w2,
    const float* __restrict__ bias,
    float* __restrict__ outF, uint32_t* __restrict__ outP, int ostride,
    int Kp, int Nc, int act)
{
    extern __shared__ uint32_t smu[];
    uint2* smA = (uint2*)smu;        // [2][128][20]
    uint2* smB = smA + 5120;         // [2][128][20]

    const int row0 = blockIdx.y * 128;
    const int col0 = blockIdx.x * 128;
    const int tid  = threadIdx.x;
    const int lane = tid & 31, warp = tid >> 5;
    const int wR = warp >> 1, wC = warp & 1;

    float acc[2][8][4] = {};
    const int nk = Kp / 16;

    {
#pragma unroll
        for (int it = 0; it < 4; it++) {
            int i = tid + it * 256;
            int r = i >> 3, c2 = (i & 7) * 2;
            cpa16(&smA[(size_t)r * 20 + c2], a2 + (size_t)(row0 + r) * Kp + c2);
            cpa16(&smB[(size_t)r * 20 + c2], w2 + (size_t)(col0 + r) * Kp + c2);
        }
        CP_COMMIT();
    }

    for (int kt = 0; kt < nk; kt++) {
        const int s = kt & 1;
        if (kt + 1 < nk) {
            const int sn = s ^ 1;
            const int k0 = (kt + 1) * 16;
#pragma unroll
            for (int it = 0; it < 4; it++) {
                int i = tid + it * 256;
                int r = i >> 3, c2 = (i & 7) * 2;
                cpa16(&smA[(size_t)(sn * 128 + r) * 20 + c2],
                      a2 + (size_t)(row0 + r) * Kp + k0 + c2);
                cpa16(&smB[(size_t)(sn * 128 + r) * 20 + c2],
                      w2 + (size_t)(col0 + r) * Kp + k0 + c2);
            }
            CP_COMMIT();
            CP_WAIT1();
        } else {
            CP_WAIT0();
        }
        __syncthreads();
#pragma unroll
        for (int ks = 0; ks < 2; ks++) {
            const int kk = ks * 8 + (lane & 3);
            uint32_t ah[2][4], al[2][4];
#pragma unroll
            for (int i = 0; i < 2; i++) {
                int m = s * 128 + wR * 32 + i * 16 + (lane >> 2);
                uint2 p0 = smA[(size_t)m * 20 + kk];
                uint2 p1 = smA[(size_t)(m + 8) * 20 + kk];
                uint2 p2 = smA[(size_t)m * 20 + kk + 4];
                uint2 p3 = smA[(size_t)(m + 8) * 20 + kk + 4];
                ah[i][0] = p0.x; ah[i][1] = p1.x; ah[i][2] = p2.x; ah[i][3] = p3.x;
                al[i][0] = p0.y; al[i][1] = p1.y; al[i][2] = p2.y; al[i][3] = p3.y;
            }
#pragma unroll
            for (int j = 0; j < 8; j++) {
                int n = s * 128 + wC * 64 + j * 8 + (lane >> 2);
                uint2 b0 = smB[(size_t)n * 20 + kk];
                uint2 b1 = smB[(size_t)n * 20 + kk + 4];
#pragma unroll
                for (int i = 0; i < 2; i++) {
                    mmabf(acc[i][j], ah[i], b0.x, b1.x);
                    mmabf(acc[i][j], ah[i], b0.y, b1.y);
                    mmabf(acc[i][j], al[i], b0.x, b1.x);
                }
            }
        }
        __syncthreads();
    }
#pragma unroll
    for (int i = 0; i < 2; i++) {
        int r = row0 + wR * 32 + i * 16 + (lane >> 2);
#pragma unroll
        for (int j = 0; j < 8; j++) {
            int c = col0 + wC * 64 + j * 8 + 2 * (lane & 3);
            float b0 = bias[c], b1 = bias[c + 1];
            float v0 = acc[i][j][0] + b0, v1 = acc[i][j][1] + b1;
            float v2 = acc[i][j][2] + b0, v3 = acc[i][j][3] + b1;
            if (act) {
                v0 = v0 / (1.0f + __expf(-v0));
                v1 = v1 / (1.0f + __expf(-v1));
                v2 = v2 / (1.0f + __expf(-v2));
                v3 = v3 / (1.0f + __expf(-v3));
            }
            if (outP) {
                uint32_t hh, ll;
                size_t o0 = ((size_t)r * (Nc >> 1) + (c >> 1)) * ostride;
                split2(v0, v1, hh, ll); *(uint2*)&outP[o0] = make_uint2(hh, ll);
                size_t o1 = ((size_t)(r + 8) * (Nc >> 1) + (c >> 1)) * ostride;
                split2(v2, v3, hh, ll); *(uint2*)&outP[o1] = make_uint2(hh, ll);
            } else {
                *(float2*)&outF[(size_t)r * Nc + c]       = make_float2(v0, v1);
                *(float2*)&outF[(size_t)(r + 8) * Nc + c] = make_float2(v2, v3);
            }
        }
    }
}

// =============================================================================
// Logits: dual bf16x3 NT GEMM from interleaved uint4 planes (R7, unchanged).
// =============================================================================
__global__ __launch_bounds__(256, 2) void logitsP_kernel(
    const float* __restrict__ pi_star, const float* __restrict__ gamma_p)
{
    extern __shared__ uint32_t smu[];
    uint4* smQ = (uint4*)smu;        // [2][128][12]
    uint4* smK = smQ + 3072;         // [2][64][12]

    const int b  = blockIdx.z;
    const int n0 = blockIdx.y * 128;
    const int m0 = blockIdx.x * 64;
    const int tid = threadIdx.x;
    const int lane = tid & 31, warp = tid >> 5;
    const int wR = warp >> 1, wC = warp & 1;

    const uint4* q4 = g_q4 + (size_t)(b * Nn + n0) * 128;
    const uint4* k4 = g_k4 + (size_t)(b * Mm + m0) * 128;

    float accS[2][4][4] = {}, accE[2][4][4] = {};
    const int nk = 16;

    {
#pragma unroll
        for (int it = 0; it < 4; it++) {
            int i = tid + it * 256;
            int r = i >> 3, kp = i & 7;
            cpa16(&smQ[(size_t)r * 12 + kp], q4 + (size_t)r * 128 + kp);
        }
#pragma unroll
        for (int it = 0; it < 2; it++) {
            int i = tid + it * 256;
            int r = i >> 3, kp = i & 7;
            cpa16(&smK[(size_t)r * 12 + kp], k4 + (size_t)r * 128 + kp);
        }
        CP_COMMIT();
    }

    for (int kt = 0; kt < nk; kt++) {
        const int s = kt & 1;
        if (kt + 1 < nk) {
            const int sn = s ^ 1;
            const int k0 = (kt + 1) * 8;
#pragma unroll
            for (int it = 0; it < 4; it++) {
                int i = tid + it * 256;
                int r = i >> 3, kp = i & 7;
                cpa16(&smQ[(size_t)(sn * 128 + r) * 12 + kp], q4 + (size_t)r * 128 + k0 + kp);
            }
#pragma unroll
            for (int it = 0; it < 2; it++) {
                int i = tid + it * 256;
                int r = i >> 3, kp = i & 7;
                cpa16(&smK[(size_t)(sn * 64 + r) * 12 + kp], k4 + (size_t)r * 128 + k0 + kp);
            }
            CP_COMMIT();
            CP_WAIT1();
        } else {
            CP_WAIT0();
        }
        __syncthreads();

        const int kk = lane & 3;
        uint32_t ash[2][4], asl[2][4], aeh[2][4], ael[2][4];
#pragma unroll
        for (int i = 0; i < 2; i++) {
            int m = s * 128 + wR * 32 + i * 16 + (lane >> 2);
            uint4 p0 = smQ[(size_t)m * 12 + kk];
            uint4 p1 = smQ[(size_t)(m + 8) * 12 + kk];
            uint4 p2 = smQ[(size_t)m * 12 + kk + 4];
            uint4 p3 = smQ[(size_t)(m + 8) * 12 + kk + 4];
            ash[i][0] = p0.x; ash[i][1] = p1.x; ash[i][2] = p2.x; ash[i][3] = p3.x;
            asl[i][0] = p0.y; asl[i][1] = p1.y; asl[i][2] = p2.y; asl[i][3] = p3.y;
            aeh[i][0] = p0.z; aeh[i][1] = p1.z; aeh[i][2] = p2.z; aeh[i][3] = p3.z;
            ael[i][0] = p0.w; ael[i][1] = p1.w; ael[i][2] = p2.w; ael[i][3] = p3.w;
        }
#pragma unroll
        for (int j = 0; j < 4; j++) {
            int n = s * 64 + wC * 32 + j * 8 + (lane >> 2);
            uint4 k0v = smK[(size_t)n * 12 + kk];
            uint4 k1v = smK[(size_t)n * 12 + kk + 4];
#pragma unroll
            for (int i = 0; i < 2; i++) {
                mmabf(accS[i][j], ash[i], k0v.x, k1v.x);
                mmabf(accS[i][j], ash[i], k0v.y, k1v.y);
                mmabf(accS[i][j], asl[i], k0v.x, k1v.x);
                mmabf(accE[i][j], aeh[i], k0v.z, k1v.z);
                mmabf(accE[i][j], aeh[i], k0v.w, k1v.w);
                mmabf(accE[i][j], ael[i], k0v.z, k1v.z);
            }
        }
        __syncthreads();
    }

    const float g = gamma_p[0];
    float sumd = 0.0f;
#pragma unroll
    for (int i = 0; i < 2; i++) {
        int n_lo = n0 + wR * 32 + i * 16 + (lane >> 2);
        float q2a = g_q2[b * Nn + n_lo];
        float q2b = g_q2[b * Nn + n_lo + 8];
#pragma unroll
        for (int j = 0; j < 4; j++) {
            int m = m0 + wC * 32 + j * 8 + 2 * (lane & 3);
            float k2a = g_k2[b * Mm + m], k2b = g_k2[b * Mm + m + 1];
            size_t base0 = ((size_t)b * Nn + n_lo) * Mm + m;
            float2 piv = *(const float2*)&pi_star[base0];
            float d0 = sqrtf(fmaxf(q2a + k2a - 2.0f * accE[i][j][0], 1e-12f));
            float d1 = sqrtf(fmaxf(q2a + k2b - 2.0f * accE[i][j][1], 1e-12f));
            sumd += d0 + d1;
            *(float2*)&g_D[base0] = make_float2(d0, d1);
            float L0 = accS[i][j][0] * 0.0625f + g * __logf(fmaxf(piv.x, 1e-9f));
            float L1 = accS[i][j][1] * 0.0625f + g * __logf(fmaxf(piv.y, 1e-9f));
            *(float2*)&g_L[base0] = make_float2(L0, L1);
            size_t base1 = ((size_t)b * Nn + n_lo + 8) * Mm + m;
            piv = *(const float2*)&pi_star[base1];
            float d2v = sqrtf(fmaxf(q2b + k2a - 2.0f * accE[i][j][2], 1e-12f));
            float d3v = sqrtf(fmaxf(q2b + k2b - 2.0f * accE[i][j][3], 1e-12f));
            sumd += d2v + d3v;
            *(float2*)&g_D[base1] = make_float2(d2v, d3v);
            float L2 = accS[i][j][2] * 0.0625f + g * __logf(fmaxf(piv.x, 1e-9f));
            float L3 = accS[i][j][3] * 0.0625f + g * __logf(fmaxf(piv.y, 1e-9f));
            *(float2*)&g_L[base1] = make_float2(L2, L3);
        }
    }
    float* red = (float*)smu;
    red[tid] = sumd;
    __syncthreads();
    for (int sred = 128; sred > 0; sred >>= 1) {
        if (tid < sred) red[tid] += red[tid + sred];
        __syncthreads();
    }
    if (tid == 0) atomicAdd(&g_dsum[b], red[0]);
}

// =============================================================================
// Ctx: dual bf16x3 NN GEMM (R7, unchanged).
// =============================================================================
__global__ __launch_bounds__(256, 2) void ctxP_kernel()
{
    extern __shared__ uint32_t smu[];
    uint2* smP = (uint2*)smu;                // [2][128][20]
    uint4* smV = (uint4*)(smu + 10240);      // [2][64][20]

    const int b  = blockIdx.z;
    const int n0 = blockIdx.y * 128;
    const int h0 = blockIdx.x * 64;
    const int tid = threadIdx.x;
    const int lane = tid & 31, warp = tid >> 5;
    const int wR = warp >> 1, wC = warp & 1;

    const uint2* p2 = g_p2 + (size_t)(b * Nn + n0) * 1024;
    const uint4* v4 = g_vT4 + ((size_t)b * Hh + h0) * 1024;

    float accS[2][4][4] = {}, accE[2][4][4] = {};
    const int nk = 64;

    {
#pragma unroll
        for (int it = 0; it < 4; it++) {
            int i = tid + it * 256;
            int r = i >> 3, c2 = (i & 7) * 2;
            cpa16(&smP[(size_t)r * 20 + c2], p2 + (size_t)r * 1024 + c2);
            int rv = i >> 4, kp = i & 15;
            cpa16(&smV[(size_t)rv * 20 + kp], v4 + (size_t)rv * 1024 + kp);
        }
        CP_COMMIT();
    }

    for (int kt = 0; kt < nk; kt++) {
        const int s = kt & 1;
        if (kt + 1 < nk) {
            const int sn = s ^ 1;
            const int mp0 = (kt + 1) * 16;
#pragma unroll
            for (int it = 0; it < 4; it++) {
                int i = tid + it * 256;
                int r = i >> 3, c2 = (i & 7) * 2;
                cpa16(&smP[(size_t)(sn * 128 + r) * 20 + c2],
                      p2 + (size_t)r * 1024 + mp0 + c2);
                int rv = i >> 4, kp = i & 15;
                cpa16(&smV[(size_t)(sn * 64 + rv) * 20 + kp],
                      v4 + (size_t)rv * 1024 + mp0 + kp);
            }
            CP_COMMIT();
            CP_WAIT1();
        } else {
            CP_WAIT0();
        }
        __syncthreads();
#pragma unroll
        for (int ks = 0; ks < 2; ks++) {
            const int kk = ks * 8 + (lane & 3);
            uint32_t ph[2][4], pl[2][4];
#pragma unroll
            for (int i = 0; i < 2; i++) {
                int m = s * 128 + wR * 32 + i * 16 + (lane >> 2);
                uint2 p0 = smP[(size_t)m * 20 + kk];
                uint2 p1 = smP[(size_t)(m + 8) * 20 + kk];
                uint2 p2v = smP[(size_t)m * 20 + kk + 4];
                uint2 p3 = smP[(size_t)(m + 8) * 20 + kk + 4];
                ph[i][0] = p0.x; ph[i][1] = p1.x; ph[i][2] = p2v.x; ph[i][3] = p3.x;
                pl[i][0] = p0.y; pl[i][1] = p1.y; pl[i][2] = p2v.y; pl[i][3] = p3.y;
            }
#pragma unroll
            for (int j = 0; j < 4; j++) {
                int n = s * 64 + wC * 32 + j * 8 + (lane >> 2);
                uint4 v0 = smV[(size_t)n * 20 + kk];
                uint4 v1 = smV[(size_t)n * 20 + kk + 4];
#pragma unroll
                for (int i = 0; i < 2; i++) {
                    mmabf(accS[i][j], ph[i], v0.x, v1.x);
                    mmabf(accS[i][j], ph[i], v0.y, v1.y);
                    mmabf(accS[i][j], pl[i], v0.x, v1.x);
                    mmabf(accE[i][j], ph[i], v0.z, v1.z);
                    mmabf(accE[i][j], ph[i], v0.w, v1.w);
                    mmabf(accE[i][j], pl[i], v0.z, v1.z);
                }
            }
        }
        __syncthreads();
    }
#pragma unroll
    for (int i = 0; i < 2; i++) {
        int n_lo = n0 + wR * 32 + i * 16 + (lane >> 2);
#pragma unroll
        for (int j = 0; j < 4; j++) {
            int h = h0 + wC * 32 + j * 8 + 2 * (lane & 3);
#pragma unroll
            for (int half = 0; half < 2; half++) {
                int n = n_lo + half * 8;
                float cs0 = accS[i][j][half * 2 + 0], cs1 = accS[i][j][half * 2 + 1];
                float ce0 = accE[i][j][half * 2 + 0], ce1 = accE[i][j][half * 2 + 1];
                size_t fb = ((size_t)b * Nn + n) * 512;
                uint32_t hh, ll;
                split2(cs0, cs1, hh, ll);             g_f2[fb + (h >> 1)]       = make_uint2(hh, ll);
                split2(ce0, ce1, hh, ll);             g_f2[fb + 128 + (h >> 1)] = make_uint2(hh, ll);
                split2(cs0 - ce0, cs1 - ce1, hh, ll); g_f2[fb + 256 + (h >> 1)] = make_uint2(hh, ll);
                split2(cs0 * ce0, cs1 * ce1, hh, ll); g_f2[fb + 384 + (h >> 1)] = make_uint2(hh, ll);
            }
        }
    }
}

// ---------------- softmax ----------------
__global__ void softmax_kernel(const float* __restrict__ ew_p) {
    const int row = blockIdx.x;
    const int b   = row / Nn;
    const float invsc = ew_p[0] / g_scale[b];
    const size_t base = (size_t)row * Mm;
    const int c0 = threadIdx.x * 8;
    float v[8];
    float mx = -1e30f;
#pragma unroll
    for (int q = 0; q < 2; q++) {
        float4 lv = *(const float4*)&g_L[base + c0 + q * 4];
        float4 dv = *(const float4*)&g_D[base + c0 + q * 4];
        v[q*4+0] = lv.x - dv.x * invsc; v[q*4+1] = lv.y - dv.y * invsc;
        v[q*4+2] = lv.z - dv.z * invsc; v[q*4+3] = lv.w - dv.w * invsc;
    }
#pragma unroll
    for (int t = 0; t < 8; t++) mx = fmaxf(mx, v[t]);
    __shared__ float sh[8];
    __shared__ float bc;
    int lane = threadIdx.x & 31, wid = threadIdx.x >> 5;
    float wm = warpRedMax(mx);
    if (lane == 0) sh[wid] = wm;
    __syncthreads();
    if (wid == 0) {
        float t = (lane < 8) ? sh[lane] : -1e30f;
        t = warpRedMax(t);
        if (lane == 0) bc = t;
    }
    __syncthreads();
    mx = bc;
    float sum = 0.0f;
#pragma unroll
    for (int t = 0; t < 8; t++) {
        v[t] = __expf(v[t] - mx);
        sum += v[t];
    }
    __syncthreads();
    float ws = warpRedSum(sum);
    if (lane == 0) sh[wid] = ws;
    __syncthreads();
    if (wid == 0) {
        float t = (lane < 8) ? sh[lane] : 0.0f;
        t = warpRedSum(t);
        if (lane == 0) bc = t;
    }
    __syncthreads();
    const float inv = 1.0f / bc;
    const size_t pbase = (size_t)row * 1024 + threadIdx.x * 4;
#pragma unroll
    for (int p = 0; p < 4; p++) {
        uint32_t hh, ll;
        split2(v[2 * p] * inv, v[2 * p + 1] * inv, hh, ll);
        g_p2[pbase + p] = make_uint2(hh, ll);
    }
}

// ---------------- launch ----------------
extern "C" void kernel_launch(void* const* d_in, const int* in_sizes, int n_in,
                              void* d_out, int out_size) {
    const float* q_fp  = (const float*)d_in[0];
    const float* v_ret = (const float*)d_in[1];
    const float* pi    = (const float*)d_in[2];
    const float* Wqs = (const float*)d_in[3];  const float* bqs = (const float*)d_in[4];
    const float* Wks = (const float*)d_in[5];  const float* bks = (const float*)d_in[6];
    const float* Wvs = (const float*)d_in[7];  const float* bvs = (const float*)d_in[8];
    const float* Wqe = (const float*)d_in[9];  const float* bqe = (const float*)d_in[10];
    const float* Wke = (const float*)d_in[11]; const float* bke = (const float*)d_in[12];
    const float* Wve = (const float*)d_in[13]; const float* bve = (const float*)d_in[14];
    const float* W1  = (const float*)d_in[15]; const float* b1  = (const float*)d_in[16];
    const float* W2  = (const float*)d_in[17]; const float* b2  = (const float*)d_in[18];
    const float* gamma = (const float*)d_in[19];
    const float* ew    = (const float*)d_in[20];
    float* out = (float*)d_out;

    uint2 *qf2, *vr2, *w2, *f2, *h2;
    uint4 *q4, *k4, *vT4;
    float *vs_p, *ve_p, *q2_p, *k2_p;
    cudaGetSymbolAddress((void**)&qf2, g_qf2);
    cudaGetSymbolAddress((void**)&vr2, g_vr2);
    cudaGetSymbolAddress((void**)&w2, g_w2);
    cudaGetSymbolAddress((void**)&q4, g_q4);
    cudaGetSymbolAddress((void**)&k4, g_k4);
    cudaGetSymbolAddress((void**)&vT4, g_vT4);
    cudaGetSymbolAddress((void**)&f2, g_f2);
    cudaGetSymbolAddress((void**)&h2, g_h2);
    cudaGetSymbolAddress((void**)&vs_p, g_vs);
    cudaGetSymbolAddress((void**)&ve_p, g_ve);
    cudaGetSymbolAddress((void**)&q2_p, g_q2);
    cudaGetSymbolAddress((void**)&k2_p, g_k2);

    const int G2_SMEM    = 6144 * 8;      // 49152
    const int GEMM_SMEM  = 81920;
    const int LOGIT_SMEM = 73728;
    const int CTX_SMEM   = 81920;
    cudaFuncSetAttribute(gemm2_kernel,   cudaFuncAttributeMaxDynamicSharedMemorySize, G2_SMEM);
    cudaFuncSetAttribute(gemmP_kernel,   cudaFuncAttributeMaxDynamicSharedMemorySize, GEMM_SMEM);
    cudaFuncSetAttribute(logitsP_kernel, cudaFuncAttributeMaxDynamicSharedMemorySize, LOGIT_SMEM);
    cudaFuncSetAttribute(ctxP_kernel,    cudaFuncAttributeMaxDynamicSharedMemorySize, CTX_SMEM);

    // weight slots: qs,ks,vs,qe,ke,ve,W1,W2
    uint2* wo[8] = {w2, w2+65536, w2+131072, w2+196608, w2+262144, w2+327680,
                    w2+393216, w2+524288};

    dim3 gp(4, (Bb * Nn) / 128);   // (4, 128) for dual-output projections

    // launch order arranged so launch index 5 (6th) = gemm2 (ncu -s 5 -c 1)
    pack_rows_kernel<<<(Bb*Nn*DIN/2 + 255)/256, 256>>>(q_fp,  qf2, Bb*Nn*DIN/2);     // 0
    pack_rows_kernel<<<(Bb*Mm*DIN/2 + 255)/256, 256>>>(v_ret, vr2, Bb*Mm*DIN/2);     // 1
    pack_weight_kernel<<<(256*256 + 255)/256, 256>>>(Wqs, wo[0], 256, 256);          // 2
    pack_weight_kernel<<<(256*256 + 255)/256, 256>>>(Wqe, wo[3], 256, 256);          // 3
    pack_weight_kernel<<<(256*256 + 255)/256, 256>>>(Wks, wo[1], 256, 256);          // 4
    gemm2_kernel<<<gp, 256, G2_SMEM>>>(qf2, wo[0], wo[3], bqs, bqe,
                                       q4, nullptr, nullptr, 256);                   // 5 <- profiled
    pack_weight_kernel<<<(256*256 + 255)/256, 256>>>(Wke, wo[4], 256, 256);
    gemm2_kernel<<<gp, 256, G2_SMEM>>>(vr2, wo[1], wo[4], bks, bke,
                                       k4, nullptr, nullptr, 256);
    pack_weight_kernel<<<(256*256 + 255)/256, 256>>>(Wvs, wo[2], 256, 256);
    pack_weight_kernel<<<(256*256 + 255)/256, 256>>>(Wve, wo[5], 256, 256);
    gemm2_kernel<<<gp, 256, G2_SMEM>>>(vr2, wo[2], wo[5], bvs, bve,
                                       nullptr, vs_p, ve_p, 256);
    pack_weight_kernel<<<(512*256 + 255)/256, 256>>>(W1, wo[6], 512, 256);
    pack_weight_kernel<<<(128*256 + 255)/256, 256>>>(W2, wo[7], 128, 256);

    dim3 gt(Mm / 64, Hh / 32, Bb);
    transpose_pack2_kernel<<<gt, 256>>>(vs_p, ve_p, vT4);

    rowsumsq_kernel<<<Bb * Nn, 128>>>(q4, q2_p);
    rowsumsq_kernel<<<Bb * Mm, 128>>>(k4, k2_p);

    zero_dsum_kernel<<<1, 32>>>();
    dim3 gl(Mm / 64, Nn / 128, Bb);
    logitsP_kernel<<<gl, 256, LOGIT_SMEM>>>(pi, gamma);
    finalize_scale_kernel<<<1, 32>>>();

    softmax_kernel<<<Bb * Nn, 256>>>(ew);

    dim3 gc(Hh / 64, Nn / 128, Bb);
    ctxP_kernel<<<gc, 256, CTX_SMEM>>>();

    dim3 gm(2, (Bb * Nn) / 128);
    gemmP_kernel<<<gm, 256, GEMM_SMEM>>>(f2, wo[6], b1, nullptr, (uint32_t*)h2, 2, 512, 256, 1);
    gemmP_kernel<<<gm, 256, GEMM_SMEM>>>(h2, wo[7], b2, out, nullptr, 0, 128, 256, 0);
}